// round 1
// baseline (speedup 1.0000x reference)
#include <cuda_runtime.h>
#include <cuda_bf16.h>
#include <math.h>

#define BATCH 64
#define TLEN  512
#define RNNH  256
#define ENCD  512
#define ZK    640
#define GATES 1024
#define LABEL 128
#define MROWS (BATCH*TLEN)          /* 32768 */
#define OUTN  (4194304)             /* MROWS*LABEL */

// ---------------- scratch (device globals; no allocation allowed) ----------------
__device__ float g_zin[(size_t)MROWS*ZK];     // [B*T,640]  pe|pool
__device__ float g_z  [(size_t)MROWS*RNNH];   // tanh(zin@Wcomb^T+b), t==0 rows zeroed
__device__ float g_G1 [(size_t)MROWS*GATES];  // z@w_ih^T + b_ih + b_hh
__device__ float g_Hw [(size_t)MROWS*RNNH];   // per-word carry h_j
__device__ float g_Cw [(size_t)MROWS*RNNH];   // per-word carry c_j
__device__ float g_H2 [(size_t)MROWS*GATES];  // Hw@w_hh^T
__device__ float g_hs [(size_t)MROWS*RNNH];   // per-step LSTM output
__device__ int   g_svec[MROWS];
__device__ int   g_cidx[MROWS];               // carry index per step (cnt-1, -1 => zeros)
__device__ int   g_bpos[MROWS];               // boundary positions per batch
__device__ int   g_wcnt[BATCH];
__device__ __nv_bfloat16 g_whh_bf[GATES*RNNH];

__device__ __forceinline__ float sigf(float x){ return 1.f/(1.f+expf(-x)); }

// ---------------- K-w: convert w_hh to bf16 (chain-only approximation) -----------
__global__ void k_convert_whh(const float* __restrict__ whh){
    int i = blockIdx.x*blockDim.x + threadIdx.x;
    if (i < GATES*RNNH) g_whh_bf[i] = __float2bfloat16(whh[i]);
}

// ---------------- K0: per-batch boundary scan metadata ---------------------------
__global__ void k_scan_meta(const int* __restrict__ bnd){
    int b = threadIdx.x;
    if (b >= BATCH) return;
    int last = 0, cnt = 0;
    for (int t = 0; t < TLEN; t++){
        g_svec[b*TLEN+t] = last;
        g_cidx[b*TLEN+t] = cnt - 1;
        if (bnd[b*TLEN+t] == 1){ g_bpos[b*TLEN+cnt] = t; cnt++; last = t; }
    }
    g_wcnt[b] = cnt;
}

// ---------------- K1: build zin = [pos_emb(128) | running word mean(512)] --------
__global__ void k_build_zin(const float* __restrict__ enc, const int* __restrict__ bnd,
                            const int* __restrict__ pos, const float* __restrict__ ptab){
    int b = blockIdx.y;
    int chunk = blockIdx.x;       // 0: pe, 1..4: pool dim chunks of 128
    int tid = threadIdx.x;        // 128 threads
    if (chunk == 0){
        for (int t = 0; t < TLEN; t++){
            int s = g_svec[b*TLEN+t];
            int p = pos[b*TLEN+s];
            g_zin[((size_t)(b*TLEN+t))*ZK + tid] = ptab[p*128 + tid];
        }
    } else {
        int dim = (chunk-1)*128 + tid;
        float acc = 0.f;
        for (int t = 0; t < TLEN; t++){
            int s = g_svec[b*TLEN+t];
            float wl = (float)((t - s) > 1 ? (t - s) : 1);
            g_zin[((size_t)(b*TLEN+t))*ZK + 128 + dim] = acc / wl;
            float x = enc[((size_t)(b*TLEN+t))*ENCD + dim];
            acc = (bnd[b*TLEN+t] == 1) ? x : (acc + x);
        }
    }
}

// ---------------- generic fp32 SIMT GEMM:  C[M,N] = A[M,K] @ W[N,K]^T ------------
// EPI 0: z = tanh(v + bias1[n]); zero rows with t==0
// EPI 1: v += bias1[n] + bias2[n]
// EPI 2: plain, skip tiles beyond word count (ragged H2)
template<int EPI>
__global__ void k_gemm_nt(const float* __restrict__ A, const float* __restrict__ W,
                          float* __restrict__ C, int K, int N,
                          const float* __restrict__ bias1, const float* __restrict__ bias2){
    int row0 = blockIdx.y * 128;
    int col0 = blockIdx.x * 128;
    if (EPI == 2){
        int b = row0 >> 9;
        if ((row0 & 511) >= g_wcnt[b]) return;   // whole tile past last word
    }
    __shared__ float As[8][128];
    __shared__ float Ws[8][128];
    int tid = threadIdx.x;                // 256
    int lr = tid >> 1;                    // 0..127
    int lk = (tid & 1) * 4;               // 0 or 4
    int ty = tid >> 4, tx = tid & 15;
    const float* Ap = A + (size_t)(row0 + lr)*K + lk;
    const float* Wp = W + (size_t)(col0 + lr)*K + lk;
    float acc[8][8];
    #pragma unroll
    for (int i=0;i<8;i++)
        #pragma unroll
        for (int j=0;j<8;j++) acc[i][j] = 0.f;
    for (int k0 = 0; k0 < K; k0 += 8){
        float4 av = *(const float4*)(Ap + k0);
        float4 wv = *(const float4*)(Wp + k0);
        As[lk+0][lr]=av.x; As[lk+1][lr]=av.y; As[lk+2][lr]=av.z; As[lk+3][lr]=av.w;
        Ws[lk+0][lr]=wv.x; Ws[lk+1][lr]=wv.y; Ws[lk+2][lr]=wv.z; Ws[lk+3][lr]=wv.w;
        __syncthreads();
        #pragma unroll
        for (int kk=0;kk<8;kk++){
            float4 a0 = *(const float4*)&As[kk][ty*8];
            float4 a1 = *(const float4*)&As[kk][ty*8+4];
            float4 w0 = *(const float4*)&Ws[kk][tx*8];
            float4 w1 = *(const float4*)&Ws[kk][tx*8+4];
            float af[8] = {a0.x,a0.y,a0.z,a0.w,a1.x,a1.y,a1.z,a1.w};
            float wf[8] = {w0.x,w0.y,w0.z,w0.w,w1.x,w1.y,w1.z,w1.w};
            #pragma unroll
            for (int i=0;i<8;i++)
                #pragma unroll
                for (int j=0;j<8;j++)
                    acc[i][j] = fmaf(af[i], wf[j], acc[i][j]);
        }
        __syncthreads();
    }
    #pragma unroll
    for (int i=0;i<8;i++){
        int m = row0 + ty*8 + i;
        #pragma unroll
        for (int j=0;j<8;j++){
            int n = col0 + tx*8 + j;
            float v = acc[i][j];
            if (EPI == 0){
                v = tanhf(v + bias1[n]);
                if ((m & (TLEN-1)) == 0) v = 0.f;     // z[:,0,:] = 0
            } else if (EPI == 1){
                v += bias1[n] + bias2[n];
            }
            C[(size_t)m*N + n] = v;
        }
    }
}

// ---------------- K4: sequential per-word carry chain (one block per batch) ------
__global__ void k_chain(){
    __shared__ float sh_h[RNNH];
    __shared__ float sh_c[RNNH];
    __shared__ float sh_g[GATES];
    int b = blockIdx.x;
    int tid = threadIdx.x;                 // 512
    if (tid < RNNH){ sh_h[tid] = 0.f; sh_c[tid] = 0.f; }
    __syncthreads();
    int Wb = g_wcnt[b];
    int o1 = tid, o2 = tid + 512;
    const uint4* w1 = (const uint4*)&g_whh_bf[(size_t)o1*RNNH];
    const uint4* w2 = (const uint4*)&g_whh_bf[(size_t)o2*RNNH];
    for (int k = 0; k < Wb; k++){
        int t = g_bpos[b*TLEN + k];
        const float* g1 = &g_G1[((size_t)(b*TLEN + t))*GATES];
        float s1 = 0.f, s2 = 0.f;
        #pragma unroll 8
        for (int q = 0; q < 32; q++){
            uint4 u1 = w1[q];
            uint4 u2 = w2[q];
            const __nv_bfloat162* p1 = (const __nv_bfloat162*)&u1;
            const __nv_bfloat162* p2 = (const __nv_bfloat162*)&u2;
            #pragma unroll
            for (int e = 0; e < 4; e++){
                float2 f1 = __bfloat1622float2(p1[e]);
                float2 f2 = __bfloat1622float2(p2[e]);
                float h0 = sh_h[q*8 + 2*e];
                float h1 = sh_h[q*8 + 2*e + 1];
                s1 = fmaf(f1.x, h0, s1); s1 = fmaf(f1.y, h1, s1);
                s2 = fmaf(f2.x, h0, s2); s2 = fmaf(f2.y, h1, s2);
            }
        }
        sh_g[o1] = g1[o1] + s1;
        sh_g[o2] = g1[o2] + s2;
        __syncthreads();
        if (tid < RNNH){
            float iv = sh_g[tid];
            float fv = sh_g[256 + tid];
            float gv = sh_g[512 + tid];
            float ov = sh_g[768 + tid];
            float cc = sigf(fv)*sh_c[tid] + sigf(iv)*tanhf(gv);
            float hh = sigf(ov)*tanhf(cc);
            sh_c[tid] = cc; sh_h[tid] = hh;
            g_Hw[((size_t)(b*TLEN + k))*RNNH + tid] = hh;
            g_Cw[((size_t)(b*TLEN + k))*RNNH + tid] = cc;
        }
        __syncthreads();
    }
}

// ---------------- K5: parallel per-step LSTM cell apply --------------------------
__global__ void k_apply(){
    int m = blockIdx.x;           // row = b*T + t
    int d = threadIdx.x;          // 256
    int b = m >> 9;
    int j = g_cidx[m];
    size_t gbase = (size_t)m*GATES;
    float iv = g_G1[gbase +       d];
    float fv = g_G1[gbase + 256 + d];
    float gv = g_G1[gbase + 512 + d];
    float ov = g_G1[gbase + 768 + d];
    float cprev = 0.f;
    if (j >= 0){
        size_t hbase = (size_t)(b*TLEN + j)*GATES;
        iv += g_H2[hbase +       d];
        fv += g_H2[hbase + 256 + d];
        gv += g_H2[hbase + 512 + d];
        ov += g_H2[hbase + 768 + d];
        cprev = g_Cw[(size_t)(b*TLEN + j)*RNNH + d];
    }
    float cc = sigf(fv)*cprev + sigf(iv)*tanhf(gv);
    g_hs[(size_t)m*RNNH + d] = sigf(ov)*tanhf(cc);
}

// ---------------- K6: logits GEMM ([hs|enc] @ linear_w^T) fused with log_softmax -
__global__ void k_out_softmax(const float* __restrict__ enc, const float* __restrict__ LW,
                              const int* __restrict__ lengths, float* __restrict__ out, int dup){
    __shared__ float As[8][128];
    __shared__ float Ws[8][128];
    int row0 = blockIdx.x * 128;
    int tid = threadIdx.x;
    int lr = tid >> 1, lk = (tid & 1) * 4;
    int ty = tid >> 4, tx = tid & 15;
    float acc[8][8];
    #pragma unroll
    for (int i=0;i<8;i++)
        #pragma unroll
        for (int j=0;j<8;j++) acc[i][j] = 0.f;
    for (int k0 = 0; k0 < 768; k0 += 8){
        int kk = k0 + lk;
        int m = row0 + lr;
        float4 av;
        if (kk < 256) av = *(const float4*)&g_hs[(size_t)m*RNNH + kk];
        else          av = *(const float4*)&enc[(size_t)m*ENCD + (kk - 256)];
        float4 wv = *(const float4*)&LW[(size_t)lr*768 + kk];
        As[lk+0][lr]=av.x; As[lk+1][lr]=av.y; As[lk+2][lr]=av.z; As[lk+3][lr]=av.w;
        Ws[lk+0][lr]=wv.x; Ws[lk+1][lr]=wv.y; Ws[lk+2][lr]=wv.z; Ws[lk+3][lr]=wv.w;
        __syncthreads();
        #pragma unroll
        for (int q=0;q<8;q++){
            float4 a0 = *(const float4*)&As[q][ty*8];
            float4 a1 = *(const float4*)&As[q][ty*8+4];
            float4 w0 = *(const float4*)&Ws[q][tx*8];
            float4 w1 = *(const float4*)&Ws[q][tx*8+4];
            float af[8] = {a0.x,a0.y,a0.z,a0.w,a1.x,a1.y,a1.z,a1.w};
            float wf[8] = {w0.x,w0.y,w0.z,w0.w,w1.x,w1.y,w1.z,w1.w};
            #pragma unroll
            for (int i=0;i<8;i++)
                #pragma unroll
                for (int j=0;j<8;j++)
                    acc[i][j] = fmaf(af[i], wf[j], acc[i][j]);
        }
        __syncthreads();
    }
    #pragma unroll
    for (int i=0;i<8;i++){
        int m = row0 + ty*8 + i;
        int b = m >> 9, t = m & 511;
        int L = lengths[b];
        float vmax = -3.0e38f;
        #pragma unroll
        for (int j=0;j<8;j++){
            float v = acc[i][j];
            int n = tx*8 + j;
            if (t == 0 && n == 0) v = -1e30f;  // APP impossible at first char
            if (t >= L) v = 0.f;               // padding rows zeroed pre-softmax
            acc[i][j] = v;
            vmax = fmaxf(vmax, v);
        }
        #pragma unroll
        for (int d=8; d>=1; d>>=1) vmax = fmaxf(vmax, __shfl_xor_sync(0xffffffffu, vmax, d, 32));
        float ssum = 0.f;
        #pragma unroll
        for (int j=0;j<8;j++) ssum += expf(acc[i][j] - vmax);
        #pragma unroll
        for (int d=8; d>=1; d>>=1) ssum += __shfl_xor_sync(0xffffffffu, ssum, d, 32);
        float lse = vmax + logf(ssum);
        #pragma unroll
        for (int j=0;j<8;j++){
            int n = tx*8 + j;
            size_t idx = (size_t)m*LABEL + n;
            float r = acc[i][j] - lse;
            out[idx] = r;
            if (dup) out[(size_t)OUTN + idx] = r;
        }
    }
}

// ---------------- launcher -------------------------------------------------------
extern "C" void kernel_launch(void* const* d_in, const int* in_sizes, int n_in,
                              void* d_out, int out_size){
    const float* enc  = (const float*)d_in[0];
    const int*   bnd  = (const int*)  d_in[1];
    const int*   pos  = (const int*)  d_in[2];
    const int*   len  = (const int*)  d_in[3];
    const float* w_ih = (const float*)d_in[4];
    const float* w_hh = (const float*)d_in[5];
    const float* b_ih = (const float*)d_in[6];
    const float* b_hh = (const float*)d_in[7];
    const float* ptab = (const float*)d_in[8];
    const float* lw   = (const float*)d_in[9];
    const float* cw   = (const float*)d_in[10];
    const float* cb   = (const float*)d_in[11];
    float* out = (float*)d_out;
    int dup = (out_size >= 2*OUTN) ? 1 : 0;

    void* p;
    cudaGetSymbolAddress(&p, g_zin); float* zin = (float*)p;
    cudaGetSymbolAddress(&p, g_z);   float* z   = (float*)p;
    cudaGetSymbolAddress(&p, g_G1);  float* G1  = (float*)p;
    cudaGetSymbolAddress(&p, g_Hw);  float* Hw  = (float*)p;
    cudaGetSymbolAddress(&p, g_H2);  float* H2  = (float*)p;

    k_convert_whh<<<256, 1024>>>(w_hh);
    k_scan_meta<<<1, 64>>>(bnd);
    k_build_zin<<<dim3(5, BATCH), 128>>>(enc, bnd, pos, ptab);
    // z = tanh(zin @ combine_w^T + combine_b), t==0 rows zeroed
    k_gemm_nt<0><<<dim3(RNNH/128, MROWS/128), 256>>>(zin, cw, z, ZK, RNNH, cb, cb);
    // G1 = z @ w_ih^T + b_ih + b_hh
    k_gemm_nt<1><<<dim3(GATES/128, MROWS/128), 256>>>(z, w_ih, G1, RNNH, GATES, b_ih, b_hh);
    // sequential per-word carry chain
    k_chain<<<BATCH, 512>>>();
    // H2 = Hw @ w_hh^T (ragged: skip tiles past word count)
    k_gemm_nt<2><<<dim3(GATES/128, MROWS/128), 256>>>(Hw, w_hh, H2, RNNH, GATES, nullptr, nullptr);
    // parallel per-step LSTM outputs
    k_apply<<<MROWS, 256>>>();
    // logits + masking + log_softmax (writes both output copies if out is the tuple)
    k_out_softmax<<<MROWS/128, 256>>>(enc, lw, len, out, dup);
}

// round 3
// speedup vs baseline: 2.3667x; 2.3667x over previous
#include <cuda_runtime.h>
#include <cuda_bf16.h>
#include <cstdint>
#include <math.h>

#define BATCH 64
#define TLEN  512
#define RNNH  256
#define ENCD  512
#define ZK    640
#define GATES 1024
#define LABEL 128
#define MROWS (BATCH*TLEN)          /* 32768 */
#define OUTN  (4194304)             /* MROWS*LABEL */

// ---------------- scratch (device globals; no allocation allowed) ----------------
__device__ float g_zin[(size_t)MROWS*ZK];     // [B*T,640]  pe|pool
__device__ float g_z  [(size_t)MROWS*RNNH];   // tanh(zin@Wcomb^T+b), t==0 rows zeroed
__device__ float g_G1 [(size_t)MROWS*GATES];  // z@w_ih^T + b_ih + b_hh
__device__ float g_Hw [(size_t)MROWS*RNNH];   // per-word carry h_j
__device__ float g_Cw [(size_t)MROWS*RNNH];   // per-word carry c_j
__device__ float g_H2 [(size_t)MROWS*GATES];  // Hw@w_hh^T
__device__ float g_hs [(size_t)MROWS*RNNH];   // per-step LSTM output
__device__ int   g_svec[MROWS];
__device__ int   g_cidx[MROWS];               // carry index per step (cnt-1, -1 => zeros)
__device__ int   g_bpos[MROWS];               // boundary positions per batch
__device__ int   g_wcnt[BATCH];
__device__ __nv_bfloat16 g_whh_bf[GATES*RNNH];

__device__ __forceinline__ float sigf(float x){ return 1.f/(1.f+expf(-x)); }

// ---------------- K-w: convert w_hh to bf16 (chain-only approximation) -----------
__global__ void k_convert_whh(const float* __restrict__ whh){
    int i = blockIdx.x*blockDim.x + threadIdx.x;
    if (i < GATES*RNNH) g_whh_bf[i] = __float2bfloat16(whh[i]);
}

// ---------------- K0: per-batch boundary scan metadata ---------------------------
__global__ void k_scan_meta(const int* __restrict__ bnd){
    int b = threadIdx.x;
    if (b >= BATCH) return;
    int last = 0, cnt = 0;
    for (int t = 0; t < TLEN; t++){
        g_svec[b*TLEN+t] = last;
        g_cidx[b*TLEN+t] = cnt - 1;
        if (bnd[b*TLEN+t] == 1){ g_bpos[b*TLEN+cnt] = t; cnt++; last = t; }
    }
    g_wcnt[b] = cnt;
}

// ---------------- K1: build zin = [pos_emb(128) | running word mean(512)] --------
__global__ void k_build_zin(const float* __restrict__ enc, const int* __restrict__ bnd,
                            const int* __restrict__ pos, const float* __restrict__ ptab){
    int b = blockIdx.y;
    int chunk = blockIdx.x;       // 0: pe, 1..4: pool dim chunks of 128
    int tid = threadIdx.x;        // 128 threads
    if (chunk == 0){
        for (int t = 0; t < TLEN; t++){
            int s = g_svec[b*TLEN+t];
            int p = pos[b*TLEN+s];
            g_zin[((size_t)(b*TLEN+t))*ZK + tid] = ptab[p*128 + tid];
        }
    } else {
        int dim = (chunk-1)*128 + tid;
        float acc = 0.f;
        for (int t = 0; t < TLEN; t++){
            int s = g_svec[b*TLEN+t];
            float wl = (float)((t - s) > 1 ? (t - s) : 1);
            g_zin[((size_t)(b*TLEN+t))*ZK + 128 + dim] = acc / wl;
            float x = enc[((size_t)(b*TLEN+t))*ENCD + dim];
            acc = (bnd[b*TLEN+t] == 1) ? x : (acc + x);
        }
    }
}

// ---------------- generic fp32 SIMT GEMM:  C[M,N] = A[M,K] @ W[N,K]^T ------------
template<int EPI>
__global__ void k_gemm_nt(const float* __restrict__ A, const float* __restrict__ W,
                          float* __restrict__ C, int K, int N,
                          const float* __restrict__ bias1, const float* __restrict__ bias2){
    int row0 = blockIdx.y * 128;
    int col0 = blockIdx.x * 128;
    if (EPI == 2){
        int b = row0 >> 9;
        if ((row0 & 511) >= g_wcnt[b]) return;   // whole tile past last word
    }
    __shared__ float As[8][128];
    __shared__ float Ws[8][128];
    int tid = threadIdx.x;                // 256
    int lr = tid >> 1;                    // 0..127
    int lk = (tid & 1) * 4;               // 0 or 4
    int ty = tid >> 4, tx = tid & 15;
    const float* Ap = A + (size_t)(row0 + lr)*K + lk;
    const float* Wp = W + (size_t)(col0 + lr)*K + lk;
    float acc[8][8];
    #pragma unroll
    for (int i=0;i<8;i++)
        #pragma unroll
        for (int j=0;j<8;j++) acc[i][j] = 0.f;
    for (int k0 = 0; k0 < K; k0 += 8){
        float4 av = *(const float4*)(Ap + k0);
        float4 wv = *(const float4*)(Wp + k0);
        As[lk+0][lr]=av.x; As[lk+1][lr]=av.y; As[lk+2][lr]=av.z; As[lk+3][lr]=av.w;
        Ws[lk+0][lr]=wv.x; Ws[lk+1][lr]=wv.y; Ws[lk+2][lr]=wv.z; Ws[lk+3][lr]=wv.w;
        __syncthreads();
        #pragma unroll
        for (int kk=0;kk<8;kk++){
            float4 a0 = *(const float4*)&As[kk][ty*8];
            float4 a1 = *(const float4*)&As[kk][ty*8+4];
            float4 w0 = *(const float4*)&Ws[kk][tx*8];
            float4 w1 = *(const float4*)&Ws[kk][tx*8+4];
            float af[8] = {a0.x,a0.y,a0.z,a0.w,a1.x,a1.y,a1.z,a1.w};
            float wf[8] = {w0.x,w0.y,w0.z,w0.w,w1.x,w1.y,w1.z,w1.w};
            #pragma unroll
            for (int i=0;i<8;i++)
                #pragma unroll
                for (int j=0;j<8;j++)
                    acc[i][j] = fmaf(af[i], wf[j], acc[i][j]);
        }
        __syncthreads();
    }
    #pragma unroll
    for (int i=0;i<8;i++){
        int m = row0 + ty*8 + i;
        #pragma unroll
        for (int j=0;j<8;j++){
            int n = col0 + tx*8 + j;
            float v = acc[i][j];
            if (EPI == 0){
                v = tanhf(v + bias1[n]);
                if ((m & (TLEN-1)) == 0) v = 0.f;     // z[:,0,:] = 0
            } else if (EPI == 1){
                v += bias1[n] + bias2[n];
            }
            C[(size_t)m*N + n] = v;
        }
    }
}

// ---------------- K4: cluster-4 carry chain, smem-resident w_hh slice ------------
// Cluster rank r owns gate chunk r (i/f/g/o, 256 rows). Weights staged transposed
// ([c2][row] bf162) for conflict-free lane-consecutive LDS. Per step: local matvec,
// DSMEM all-gather of the 4 gate chunks (double-buffered), one cluster barrier,
// redundant cell update in all ranks.
#define CH_SMEM (131072 + 1024 + 1024 + 8192)
extern __shared__ char chsm[];

__global__ void __cluster_dims__(4,1,1) __launch_bounds__(256, 1) k_chain(){
    __nv_bfloat162* sw = (__nv_bfloat162*)chsm;          // [128][256] c2-major, 128KB
    float* sh_h = (float*)(chsm + 131072);               // 256
    float* sh_c = sh_h + 256;                            // 256
    float* gbuf = sh_c + 256;                            // [2][4][256]
    int tid = threadIdx.x;                               // 256
    unsigned int r; asm("mov.u32 %0, %%cluster_ctarank;" : "=r"(r));
    int b = blockIdx.x >> 2;

    // stage weight slice rows [r*256, r*256+256) transposed
    const __nv_bfloat162* wsrc = (const __nv_bfloat162*)&g_whh_bf[((size_t)r*256)*256];
    for (int idx = tid; idx < 256*128; idx += 256){
        int row = idx >> 7, c2 = idx & 127;
        sw[c2*256 + row] = wsrc[row*128 + c2];
    }
    sh_h[tid] = 0.f; sh_c[tid] = 0.f;
    __syncthreads();

    int Wb = g_wcnt[b];
    // peer addresses of gbuf[0][r][tid] in each cluster CTA
    unsigned int l0 = (unsigned int)__cvta_generic_to_shared(&gbuf[r*256 + tid]);
    unsigned int peer[4];
    #pragma unroll
    for (int q = 0; q < 4; q++)
        asm("mapa.shared::cluster.u32 %0, %1, %2;" : "=r"(peer[q]) : "r"(l0), "r"(q));

    const float4* sh_h4 = (const float4*)sh_h;
    const float* g1base = &g_G1[((size_t)b*TLEN)*GATES + r*256 + tid];
    unsigned int p = 0;
    for (int k = 0; k < Wb; k++){
        int t = g_bpos[b*TLEN + k];
        float g1 = g1base[(size_t)t*GATES];
        float s = 0.f;
        #pragma unroll 8
        for (int c2b = 0; c2b < 32; c2b++){
            float4 ha = sh_h4[c2b*2];
            float4 hb = sh_h4[c2b*2+1];
            float2 w0 = __bfloat1622float2(sw[(c2b*4+0)*256 + tid]);
            float2 w1 = __bfloat1622float2(sw[(c2b*4+1)*256 + tid]);
            float2 w2 = __bfloat1622float2(sw[(c2b*4+2)*256 + tid]);
            float2 w3 = __bfloat1622float2(sw[(c2b*4+3)*256 + tid]);
            s = fmaf(w0.x, ha.x, s); s = fmaf(w0.y, ha.y, s);
            s = fmaf(w1.x, ha.z, s); s = fmaf(w1.y, ha.w, s);
            s = fmaf(w2.x, hb.x, s); s = fmaf(w2.y, hb.y, s);
            s = fmaf(w3.x, hb.z, s); s = fmaf(w3.y, hb.w, s);
        }
        float gate = g1 + s;
        // broadcast our gate chunk element into every cluster CTA's gbuf[p][r][tid]
        unsigned int poff = p * 4096u;  // parity stride in bytes (1024 floats)
        #pragma unroll
        for (int q = 0; q < 4; q++)
            asm volatile("st.shared::cluster.f32 [%0], %1;"
                         :: "r"(peer[q] + poff), "f"(gate) : "memory");
        asm volatile("barrier.cluster.arrive.aligned;" ::: "memory");
        asm volatile("barrier.cluster.wait.aligned;"   ::: "memory");
        const float* gb = gbuf + p*1024;
        float iv = gb[tid], fv = gb[256+tid], gv = gb[512+tid], ov = gb[768+tid];
        float cc = sigf(fv)*sh_c[tid] + sigf(iv)*tanhf(gv);
        float hh = sigf(ov)*tanhf(cc);
        sh_c[tid] = cc; sh_h[tid] = hh;
        if (r == 0) g_Hw[((size_t)(b*TLEN + k))*RNNH + tid] = hh;
        if (r == 1) g_Cw[((size_t)(b*TLEN + k))*RNNH + tid] = cc;
        p ^= 1;
        __syncthreads();
    }
    asm volatile("barrier.cluster.arrive.aligned;" ::: "memory");
    asm volatile("barrier.cluster.wait.aligned;"   ::: "memory");
}

// ---------------- K5: parallel per-step LSTM cell apply --------------------------
__global__ void k_apply(){
    int m = blockIdx.x;           // row = b*T + t
    int d = threadIdx.x;          // 256
    int b = m >> 9;
    int j = g_cidx[m];
    size_t gbase = (size_t)m*GATES;
    float iv = g_G1[gbase +       d];
    float fv = g_G1[gbase + 256 + d];
    float gv = g_G1[gbase + 512 + d];
    float ov = g_G1[gbase + 768 + d];
    float cprev = 0.f;
    if (j >= 0){
        size_t hbase = (size_t)(b*TLEN + j)*GATES;
        iv += g_H2[hbase +       d];
        fv += g_H2[hbase + 256 + d];
        gv += g_H2[hbase + 512 + d];
        ov += g_H2[hbase + 768 + d];
        cprev = g_Cw[(size_t)(b*TLEN + j)*RNNH + d];
    }
    float cc = sigf(fv)*cprev + sigf(iv)*tanhf(gv);
    g_hs[(size_t)m*RNNH + d] = sigf(ov)*tanhf(cc);
}

// ---------------- K6: logits GEMM ([hs|enc] @ linear_w^T) fused with log_softmax -
__global__ void k_out_softmax(const float* __restrict__ enc, const float* __restrict__ LW,
                              const int* __restrict__ lengths, float* __restrict__ out, int dup){
    __shared__ float As[8][128];
    __shared__ float Ws[8][128];
    int row0 = blockIdx.x * 128;
    int tid = threadIdx.x;
    int lr = tid >> 1, lk = (tid & 1) * 4;
    int ty = tid >> 4, tx = tid & 15;
    float acc[8][8];
    #pragma unroll
    for (int i=0;i<8;i++)
        #pragma unroll
        for (int j=0;j<8;j++) acc[i][j] = 0.f;
    for (int k0 = 0; k0 < 768; k0 += 8){
        int kk = k0 + lk;
        int m = row0 + lr;
        float4 av;
        if (kk < 256) av = *(const float4*)&g_hs[(size_t)m*RNNH + kk];
        else          av = *(const float4*)&enc[(size_t)m*ENCD + (kk - 256)];
        float4 wv = *(const float4*)&LW[(size_t)lr*768 + kk];
        As[lk+0][lr]=av.x; As[lk+1][lr]=av.y; As[lk+2][lr]=av.z; As[lk+3][lr]=av.w;
        Ws[lk+0][lr]=wv.x; Ws[lk+1][lr]=wv.y; Ws[lk+2][lr]=wv.z; Ws[lk+3][lr]=wv.w;
        __syncthreads();
        #pragma unroll
        for (int q=0;q<8;q++){
            float4 a0 = *(const float4*)&As[q][ty*8];
            float4 a1 = *(const float4*)&As[q][ty*8+4];
            float4 w0 = *(const float4*)&Ws[q][tx*8];
            float4 w1 = *(const float4*)&Ws[q][tx*8+4];
            float af[8] = {a0.x,a0.y,a0.z,a0.w,a1.x,a1.y,a1.z,a1.w};
            float wf[8] = {w0.x,w0.y,w0.z,w0.w,w1.x,w1.y,w1.z,w1.w};
            #pragma unroll
            for (int i=0;i<8;i++)
                #pragma unroll
                for (int j=0;j<8;j++)
                    acc[i][j] = fmaf(af[i], wf[j], acc[i][j]);
        }
        __syncthreads();
    }
    #pragma unroll
    for (int i=0;i<8;i++){
        int m = row0 + ty*8 + i;
        int b = m >> 9, t = m & 511;
        int L = lengths[b];
        float vmax = -3.0e38f;
        #pragma unroll
        for (int j=0;j<8;j++){
            float v = acc[i][j];
            int n = tx*8 + j;
            if (t == 0 && n == 0) v = -1e30f;  // APP impossible at first char
            if (t >= L) v = 0.f;               // padding rows zeroed pre-softmax
            acc[i][j] = v;
            vmax = fmaxf(vmax, v);
        }
        #pragma unroll
        for (int d=8; d>=1; d>>=1) vmax = fmaxf(vmax, __shfl_xor_sync(0xffffffffu, vmax, d, 32));
        float ssum = 0.f;
        #pragma unroll
        for (int j=0;j<8;j++) ssum += expf(acc[i][j] - vmax);
        #pragma unroll
        for (int d=8; d>=1; d>>=1) ssum += __shfl_xor_sync(0xffffffffu, ssum, d, 32);
        float lse = vmax + logf(ssum);
        #pragma unroll
        for (int j=0;j<8;j++){
            int n = tx*8 + j;
            size_t idx = (size_t)m*LABEL + n;
            float r = acc[i][j] - lse;
            out[idx] = r;
            if (dup) out[(size_t)OUTN + idx] = r;
        }
    }
}

// ---------------- launcher -------------------------------------------------------
extern "C" void kernel_launch(void* const* d_in, const int* in_sizes, int n_in,
                              void* d_out, int out_size){
    const float* enc  = (const float*)d_in[0];
    const int*   bnd  = (const int*)  d_in[1];
    const int*   pos  = (const int*)  d_in[2];
    const int*   len  = (const int*)  d_in[3];
    const float* w_ih = (const float*)d_in[4];
    const float* w_hh = (const float*)d_in[5];
    const float* b_ih = (const float*)d_in[6];
    const float* b_hh = (const float*)d_in[7];
    const float* ptab = (const float*)d_in[8];
    const float* lw   = (const float*)d_in[9];
    const float* cw   = (const float*)d_in[10];
    const float* cb   = (const float*)d_in[11];
    float* out = (float*)d_out;
    int dup = (out_size >= 2*OUTN) ? 1 : 0;

    void* p;
    cudaGetSymbolAddress(&p, g_zin); float* zin = (float*)p;
    cudaGetSymbolAddress(&p, g_z);   float* z   = (float*)p;
    cudaGetSymbolAddress(&p, g_G1);  float* G1  = (float*)p;
    cudaGetSymbolAddress(&p, g_Hw);  float* Hw  = (float*)p;
    cudaGetSymbolAddress(&p, g_H2);  float* H2  = (float*)p;

    static int attr_done = 0;
    if (!attr_done){
        cudaFuncSetAttribute(k_chain, cudaFuncAttributeMaxDynamicSharedMemorySize, CH_SMEM);
        attr_done = 1;
    }

    k_convert_whh<<<256, 1024>>>(w_hh);
    k_scan_meta<<<1, 64>>>(bnd);
    k_build_zin<<<dim3(5, BATCH), 128>>>(enc, bnd, pos, ptab);
    // z = tanh(zin @ combine_w^T + combine_b), t==0 rows zeroed
    k_gemm_nt<0><<<dim3(RNNH/128, MROWS/128), 256>>>(zin, cw, z, ZK, RNNH, cb, cb);
    // G1 = z @ w_ih^T + b_ih + b_hh
    k_gemm_nt<1><<<dim3(GATES/128, MROWS/128), 256>>>(z, w_ih, G1, RNNH, GATES, b_ih, b_hh);
    // sequential per-word carry chain: 64 clusters of 4 CTAs
    k_chain<<<BATCH*4, 256, CH_SMEM>>>();
    // H2 = Hw @ w_hh^T (ragged: skip tiles past word count)
    k_gemm_nt<2><<<dim3(GATES/128, MROWS/128), 256>>>(Hw, w_hh, H2, RNNH, GATES, nullptr, nullptr);
    // parallel per-step LSTM outputs
    k_apply<<<MROWS, 256>>>();
    // logits + masking + log_softmax (writes both output copies if out is the tuple)
    k_out_softmax<<<MROWS/128, 256>>>(enc, lw, len, out, dup);
}

// round 5
// speedup vs baseline: 3.7575x; 1.5876x over previous
#include <cuda_runtime.h>
#include <cuda_bf16.h>
#include <cstdint>
#include <math.h>

#define BATCH 64
#define TLEN  512
#define RNNH  256
#define ENCD  512
#define ZK    640
#define GATES 1024
#define LABEL 128
#define MROWS (BATCH*TLEN)          /* 32768 */
#define OUTN  (4194304)             /* MROWS*LABEL */

typedef __nv_bfloat16 bf16;

// ---------------- scratch (device globals; no allocation allowed) ----------------
__device__ __align__(16) bf16  g_zinb[(size_t)MROWS*ZK];    // [B*T,640] pe|pool (bf16)
__device__ __align__(16) bf16  g_zb  [(size_t)MROWS*RNNH];  // z (bf16)
__device__ __align__(16) float g_G1 [(size_t)MROWS*GATES];  // z@w_ih^T + b_ih + b_hh
__device__ __align__(16) bf16  g_Hwb[(size_t)MROWS*RNNH];   // per-word carry h_j (bf16)
__device__ __align__(16) float g_Cw [(size_t)MROWS*RNNH];   // per-word carry c_j
__device__ __align__(16) float g_H2 [(size_t)MROWS*GATES];  // Hw@w_hh^T
__device__ __align__(16) bf16  g_hsb[(size_t)MROWS*RNNH];   // per-step LSTM output (bf16)
__device__ __align__(16) bf16  g_encb[(size_t)MROWS*ENCD];  // encoder_out bf16
__device__ __align__(16) bf16  g_cwb [RNNH*ZK];
__device__ __align__(16) bf16  g_wihb[GATES*RNNH];
__device__ __align__(16) bf16  g_whh_bf[GATES*RNNH];
__device__ __align__(16) bf16  g_lwb [LABEL*768];
__device__ int   g_svec[MROWS];
__device__ int   g_cidx[MROWS];
__device__ int   g_bpos[MROWS];
__device__ int   g_wcnt[BATCH];

__device__ __forceinline__ float sigf(float x){ return 1.f/(1.f+expf(-x)); }

// ---------------- f32 -> bf16 conversion ----------------------------------------
__global__ void k_f2bf(const float* __restrict__ src, bf16* __restrict__ dst, int n){
    int i = (blockIdx.x*blockDim.x + threadIdx.x)*4;
    if (i < n){
        float4 v = *(const float4*)(src + i);
        __nv_bfloat162* d = (__nv_bfloat162*)(dst + i);
        d[0] = __floats2bfloat162_rn(v.x, v.y);
        d[1] = __floats2bfloat162_rn(v.z, v.w);
    }
}

// ---------------- K0: per-batch boundary scan metadata ---------------------------
__global__ void k_scan_meta(const int* __restrict__ bnd){
    int b = threadIdx.x;
    if (b >= BATCH) return;
    int last = 0, cnt = 0;
    for (int t = 0; t < TLEN; t++){
        g_svec[b*TLEN+t] = last;
        g_cidx[b*TLEN+t] = cnt - 1;
        if (bnd[b*TLEN+t] == 1){ g_bpos[b*TLEN+cnt] = t; cnt++; last = t; }
    }
    g_wcnt[b] = cnt;
}

// ---------------- K1: build zin = [pos_emb(128) | running word mean(512)] --------
__global__ void k_build_zin(const float* __restrict__ enc, const int* __restrict__ bnd,
                            const int* __restrict__ pos, const float* __restrict__ ptab){
    int b = blockIdx.y;
    int chunk = blockIdx.x;       // 0: pe, 1..4: pool dim chunks of 128
    int tid = threadIdx.x;        // 128 threads
    if (chunk == 0){
        for (int t = 0; t < TLEN; t++){
            int s = g_svec[b*TLEN+t];
            int p = pos[b*TLEN+s];
            g_zinb[((size_t)(b*TLEN+t))*ZK + tid] = __float2bfloat16(ptab[p*128 + tid]);
        }
    } else {
        int dim = (chunk-1)*128 + tid;
        float acc = 0.f;
        for (int t = 0; t < TLEN; t++){
            int s = g_svec[b*TLEN+t];
            float wl = (float)((t - s) > 1 ? (t - s) : 1);
            g_zinb[((size_t)(b*TLEN+t))*ZK + 128 + dim] = __float2bfloat16(acc / wl);
            float x = enc[((size_t)(b*TLEN+t))*ENCD + dim];
            acc = (bnd[b*TLEN+t] == 1) ? x : (acc + x);
        }
    }
}

// ================= bf16 tensor-core GEMM: C[M,N] = A[M,K] @ W[N,K]^T ==============
// BM=128, BN=128, BK=32, 256 threads (8 warps as 4x2), warp tile 32x64.
// EPI 0: Cb = bf16(tanh(acc + bias1[n])), zero rows with (m%512)==0
// EPI 1: Cf = acc + bias1[n] + bias2[n]
// EPI 2: Cf = acc, skip row tiles fully past word count
#define SSTR 40  /* smem row stride in bf16 elems (80B, conflict-free for ldmatrix) */

__device__ __forceinline__ void ldm_x4(unsigned addr, unsigned& r0, unsigned& r1,
                                       unsigned& r2, unsigned& r3){
    asm volatile("ldmatrix.sync.aligned.m8n8.x4.shared.b16 {%0,%1,%2,%3}, [%4];"
                 : "=r"(r0), "=r"(r1), "=r"(r2), "=r"(r3) : "r"(addr));
}
__device__ __forceinline__ void mma16816(float* c, const unsigned* a, const unsigned* b){
    asm volatile("mma.sync.aligned.m16n8k16.row.col.f32.bf16.bf16.f32 "
                 "{%0,%1,%2,%3}, {%4,%5,%6,%7}, {%8,%9}, {%0,%1,%2,%3};"
                 : "+f"(c[0]), "+f"(c[1]), "+f"(c[2]), "+f"(c[3])
                 : "r"(a[0]), "r"(a[1]), "r"(a[2]), "r"(a[3]), "r"(b[0]), "r"(b[1]));
}

template<int EPI>
__global__ void __launch_bounds__(256) k_gemm_mma(
        const bf16* __restrict__ A, const bf16* __restrict__ W,
        float* __restrict__ Cf, bf16* __restrict__ Cb, int K, int N,
        const float* __restrict__ bias1, const float* __restrict__ bias2){
    int row0 = blockIdx.y * 128;
    int col0 = blockIdx.x * 128;
    if (EPI == 2){
        int b = row0 >> 9;
        if ((row0 & 511) >= g_wcnt[b]) return;
    }
    __shared__ bf16 sA[128*SSTR];
    __shared__ bf16 sW[128*SSTR];
    int tid = threadIdx.x;
    int lane = tid & 31, wid = tid >> 5;
    int warp_m = wid & 3, warp_n = wid >> 2;
    int lrow = tid >> 2, lseg = tid & 3;

    const bf16* Ap = A + (size_t)(row0 + lrow)*K + lseg*8;
    const bf16* Wp = W + (size_t)(col0 + lrow)*K + lseg*8;

    unsigned sAb = (unsigned)__cvta_generic_to_shared(sA);
    unsigned sWb = (unsigned)__cvta_generic_to_shared(sW);
    unsigned aAddr = sAb + (unsigned)(((warp_m*32 + (lane&15))*SSTR + (lane>>4)*8)*2);
    unsigned bAddr = sWb + (unsigned)(((warp_n*64 + ((lane>>4)<<3) + (lane&7))*SSTR
                                      + ((lane>>3)&1)*8)*2);
    float acc[2][8][4];
    #pragma unroll
    for (int mi=0;mi<2;mi++)
        #pragma unroll
        for (int j=0;j<8;j++)
            #pragma unroll
            for (int q=0;q<4;q++) acc[mi][j][q] = 0.f;

    for (int k0 = 0; k0 < K; k0 += 32){
        uint4 a0 = *(const uint4*)(Ap + k0);
        uint4 a1 = *(const uint4*)(Ap + (size_t)64*K + k0);
        uint4 w0 = *(const uint4*)(Wp + k0);
        uint4 w1 = *(const uint4*)(Wp + (size_t)64*K + k0);
        *(uint4*)&sA[lrow*SSTR + lseg*8]       = a0;
        *(uint4*)&sA[(lrow+64)*SSTR + lseg*8]  = a1;
        *(uint4*)&sW[lrow*SSTR + lseg*8]       = w0;
        *(uint4*)&sW[(lrow+64)*SSTR + lseg*8]  = w1;
        __syncthreads();
        #pragma unroll
        for (int ks = 0; ks < 32; ks += 16){
            unsigned af[2][4], bfg[4][4];
            #pragma unroll
            for (int mi=0;mi<2;mi++)
                ldm_x4(aAddr + mi*16*SSTR*2 + ks*2, af[mi][0],af[mi][1],af[mi][2],af[mi][3]);
            #pragma unroll
            for (int p=0;p<4;p++)
                ldm_x4(bAddr + p*16*SSTR*2 + ks*2, bfg[p][0],bfg[p][1],bfg[p][2],bfg[p][3]);
            #pragma unroll
            for (int mi=0;mi<2;mi++)
                #pragma unroll
                for (int j=0;j<8;j++)
                    mma16816(acc[mi][j], af[mi], &bfg[j>>1][(j&1)*2]);
        }
        __syncthreads();
    }
    // epilogue
    #pragma unroll
    for (int mi=0;mi<2;mi++){
        #pragma unroll
        for (int j=0;j<8;j++){
            #pragma unroll
            for (int q=0;q<2;q++){
                int m = row0 + warp_m*32 + mi*16 + q*8 + (lane>>2);
                int n = col0 + warp_n*64 + j*8 + (lane&3)*2;
                float v0 = acc[mi][j][q*2+0];
                float v1 = acc[mi][j][q*2+1];
                if (EPI == 0){
                    v0 = tanhf(v0 + bias1[n]);
                    v1 = tanhf(v1 + bias1[n+1]);
                    if ((m & 511) == 0){ v0 = 0.f; v1 = 0.f; }
                    *(__nv_bfloat162*)&Cb[(size_t)m*N + n] = __floats2bfloat162_rn(v0, v1);
                } else if (EPI == 1){
                    v0 += bias1[n]   + bias2[n];
                    v1 += bias1[n+1] + bias2[n+1];
                    *(float2*)&Cf[(size_t)m*N + n] = make_float2(v0, v1);
                } else {
                    *(float2*)&Cf[(size_t)m*N + n] = make_float2(v0, v1);
                }
            }
        }
    }
}

// ---------------- K4: cluster-4 carry chain, smem-resident w_hh slice ------------
#define CH_SMEM (131072 + 1024 + 1024 + 8192)
extern __shared__ char chsm[];

__global__ void __cluster_dims__(4,1,1) __launch_bounds__(256, 1) k_chain(){
    __nv_bfloat162* sw = (__nv_bfloat162*)chsm;          // [128][256] c2-major, 128KB
    float* sh_h = (float*)(chsm + 131072);
    float* sh_c = sh_h + 256;
    float* gbuf = sh_c + 256;                            // [2][4][256]
    int tid = threadIdx.x;                               // 256
    unsigned int r; asm("mov.u32 %0, %%cluster_ctarank;" : "=r"(r));
    int b = blockIdx.x >> 2;

    const __nv_bfloat162* wsrc = (const __nv_bfloat162*)&g_whh_bf[((size_t)r*256)*256];
    for (int idx = tid; idx < 256*128; idx += 256){
        int row = idx >> 7, c2 = idx & 127;
        sw[c2*256 + row] = wsrc[row*128 + c2];
    }
    sh_h[tid] = 0.f; sh_c[tid] = 0.f;
    __syncthreads();

    int Wb = g_wcnt[b];
    unsigned int l0 = (unsigned int)__cvta_generic_to_shared(&gbuf[r*256 + tid]);
    unsigned int peer[4];
    #pragma unroll
    for (int q = 0; q < 4; q++)
        asm("mapa.shared::cluster.u32 %0, %1, %2;" : "=r"(peer[q]) : "r"(l0), "r"(q));

    const float4* sh_h4 = (const float4*)sh_h;
    const float* g1base = &g_G1[((size_t)b*TLEN)*GATES + r*256 + tid];
    unsigned int p = 0;
    for (int k = 0; k < Wb; k++){
        int t = g_bpos[b*TLEN + k];
        float g1 = g1base[(size_t)t*GATES];
        float s = 0.f;
        #pragma unroll 8
        for (int c2b = 0; c2b < 32; c2b++){
            float4 ha = sh_h4[c2b*2];
            float4 hb = sh_h4[c2b*2+1];
            float2 w0 = __bfloat1622float2(sw[(c2b*4+0)*256 + tid]);
            float2 w1 = __bfloat1622float2(sw[(c2b*4+1)*256 + tid]);
            float2 w2 = __bfloat1622float2(sw[(c2b*4+2)*256 + tid]);
            float2 w3 = __bfloat1622float2(sw[(c2b*4+3)*256 + tid]);
            s = fmaf(w0.x, ha.x, s); s = fmaf(w0.y, ha.y, s);
            s = fmaf(w1.x, ha.z, s); s = fmaf(w1.y, ha.w, s);
            s = fmaf(w2.x, hb.x, s); s = fmaf(w2.y, hb.y, s);
            s = fmaf(w3.x, hb.z, s); s = fmaf(w3.y, hb.w, s);
        }
        float gate = g1 + s;
        unsigned int poff = p * 4096u;
        #pragma unroll
        for (int q = 0; q < 4; q++)
            asm volatile("st.shared::cluster.f32 [%0], %1;"
                         :: "r"(peer[q] + poff), "f"(gate) : "memory");
        asm volatile("barrier.cluster.arrive.aligned;" ::: "memory");
        asm volatile("barrier.cluster.wait.aligned;"   ::: "memory");
        const float* gb = gbuf + p*1024;
        float iv = gb[tid], fv = gb[256+tid], gv = gb[512+tid], ov = gb[768+tid];
        float cc = sigf(fv)*sh_c[tid] + sigf(iv)*tanhf(gv);
        float hh = sigf(ov)*tanhf(cc);
        sh_c[tid] = cc; sh_h[tid] = hh;
        if (r == 0) g_Hwb[((size_t)(b*TLEN + k))*RNNH + tid] = __float2bfloat16(hh);
        if (r == 1) g_Cw [((size_t)(b*TLEN + k))*RNNH + tid] = cc;
        p ^= 1;
        __syncthreads();
    }
    asm volatile("barrier.cluster.arrive.aligned;" ::: "memory");
    asm volatile("barrier.cluster.wait.aligned;"   ::: "memory");
}

// ---------------- K5: parallel per-step LSTM cell apply --------------------------
__global__ void k_apply(){
    int m = blockIdx.x;
    int d = threadIdx.x;          // 256
    int b = m >> 9;
    int j = g_cidx[m];
    size_t gbase = (size_t)m*GATES;
    float iv = g_G1[gbase +       d];
    float fv = g_G1[gbase + 256 + d];
    float gv = g_G1[gbase + 512 + d];
    float ov = g_G1[gbase + 768 + d];
    float cprev = 0.f;
    if (j >= 0){
        size_t hbase = (size_t)(b*TLEN + j)*GATES;
        iv += g_H2[hbase +       d];
        fv += g_H2[hbase + 256 + d];
        gv += g_H2[hbase + 512 + d];
        ov += g_H2[hbase + 768 + d];
        cprev = g_Cw[(size_t)(b*TLEN + j)*RNNH + d];
    }
    float cc = sigf(fv)*cprev + sigf(iv)*tanhf(gv);
    g_hsb[(size_t)m*RNNH + d] = __float2bfloat16(sigf(ov)*tanhf(cc));
}

// ---------------- K6: logits mma GEMM ([hs|enc] @ lw^T) + fused log_softmax ------
#define LG_SMEM (128*132*4)
__global__ void __launch_bounds__(256) k_logits(const int* __restrict__ lengths,
                                                float* __restrict__ out, int dup){
    __shared__ bf16 sA[128*SSTR];
    __shared__ bf16 sW[128*SSTR];
    float* sC = (float*)chsm;    // [128][132]
    int row0 = blockIdx.x * 128;
    int tid = threadIdx.x;
    int lane = tid & 31, wid = tid >> 5;
    int warp_m = wid & 3, warp_n = wid >> 2;
    int lrow = tid >> 2, lseg = tid & 3;

    unsigned sAb = (unsigned)__cvta_generic_to_shared(sA);
    unsigned sWb = (unsigned)__cvta_generic_to_shared(sW);
    unsigned aAddr = sAb + (unsigned)(((warp_m*32 + (lane&15))*SSTR + (lane>>4)*8)*2);
    unsigned bAddr = sWb + (unsigned)(((warp_n*64 + ((lane>>4)<<3) + (lane&7))*SSTR
                                      + ((lane>>3)&1)*8)*2);
    float acc[2][8][4];
    #pragma unroll
    for (int mi=0;mi<2;mi++)
        #pragma unroll
        for (int j=0;j<8;j++)
            #pragma unroll
            for (int q=0;q<4;q++) acc[mi][j][q] = 0.f;

    for (int k0 = 0; k0 < 768; k0 += 32){
        int kk = k0 + lseg*8;
        int m0 = row0 + lrow;
        uint4 a0, a1;
        if (kk < 256){
            a0 = *(const uint4*)&g_hsb[(size_t)m0*RNNH + kk];
            a1 = *(const uint4*)&g_hsb[(size_t)(m0+64)*RNNH + kk];
        } else {
            a0 = *(const uint4*)&g_encb[(size_t)m0*ENCD + kk - 256];
            a1 = *(const uint4*)&g_encb[(size_t)(m0+64)*ENCD + kk - 256];
        }
        uint4 w0 = *(const uint4*)&g_lwb[(size_t)lrow*768 + kk];
        uint4 w1 = *(const uint4*)&g_lwb[(size_t)(lrow+64)*768 + kk];
        *(uint4*)&sA[lrow*SSTR + lseg*8]      = a0;
        *(uint4*)&sA[(lrow+64)*SSTR + lseg*8] = a1;
        *(uint4*)&sW[lrow*SSTR + lseg*8]      = w0;
        *(uint4*)&sW[(lrow+64)*SSTR + lseg*8] = w1;
        __syncthreads();
        #pragma unroll
        for (int ks = 0; ks < 32; ks += 16){
            unsigned af[2][4], bfg[4][4];
            #pragma unroll
            for (int mi=0;mi<2;mi++)
                ldm_x4(aAddr + mi*16*SSTR*2 + ks*2, af[mi][0],af[mi][1],af[mi][2],af[mi][3]);
            #pragma unroll
            for (int p=0;p<4;p++)
                ldm_x4(bAddr + p*16*SSTR*2 + ks*2, bfg[p][0],bfg[p][1],bfg[p][2],bfg[p][3]);
            #pragma unroll
            for (int mi=0;mi<2;mi++)
                #pragma unroll
                for (int j=0;j<8;j++)
                    mma16816(acc[mi][j], af[mi], &bfg[j>>1][(j&1)*2]);
        }
        __syncthreads();
    }
    // stage logits tile in smem
    #pragma unroll
    for (int mi=0;mi<2;mi++)
        #pragma unroll
        for (int j=0;j<8;j++)
            #pragma unroll
            for (int q=0;q<2;q++){
                int rl = warp_m*32 + mi*16 + q*8 + (lane>>2);
                int cl = warp_n*64 + j*8 + (lane&3)*2;
                *(float2*)&sC[rl*132 + cl] = make_float2(acc[mi][j][q*2], acc[mi][j][q*2+1]);
            }
    __syncthreads();
    // per-row log_softmax: warp w handles rows w*16..w*16+15, lane covers 4 cols
    for (int rr = 0; rr < 16; rr++){
        int rl = wid*16 + rr;
        int m = row0 + rl;
        int b = m >> 9, t = m & 511;
        int L = lengths[b];
        float v[4];
        float vmax = -3.0e38f;
        #pragma unroll
        for (int u=0;u<4;u++){
            int n = lane + u*32;
            float x = sC[rl*132 + n];
            if (t == 0 && n == 0) x = -1e30f;
            if (t >= L) x = 0.f;
            v[u] = x;
            vmax = fmaxf(vmax, x);
        }
        #pragma unroll
        for (int d=16; d>=1; d>>=1) vmax = fmaxf(vmax, __shfl_xor_sync(0xffffffffu, vmax, d, 32));
        float ssum = 0.f;
        #pragma unroll
        for (int u=0;u<4;u++) ssum += expf(v[u] - vmax);
        #pragma unroll
        for (int d=16; d>=1; d>>=1) ssum += __shfl_xor_sync(0xffffffffu, ssum, d, 32);
        float lse = vmax + logf(ssum);
        #pragma unroll
        for (int u=0;u<4;u++){
            int n = lane + u*32;
            size_t idx = (size_t)m*LABEL + n;
            float r = v[u] - lse;
            out[idx] = r;
            if (dup) out[(size_t)OUTN + idx] = r;
        }
    }
}

// ---------------- launcher -------------------------------------------------------
extern "C" void kernel_launch(void* const* d_in, const int* in_sizes, int n_in,
                              void* d_out, int out_size){
    const float* enc  = (const float*)d_in[0];
    const int*   bnd  = (const int*)  d_in[1];
    const int*   pos  = (const int*)  d_in[2];
    const int*   len  = (const int*)  d_in[3];
    const float* w_ih = (const float*)d_in[4];
    const float* w_hh = (const float*)d_in[5];
    const float* b_ih = (const float*)d_in[6];
    const float* b_hh = (const float*)d_in[7];
    const float* ptab = (const float*)d_in[8];
    const float* lw   = (const float*)d_in[9];
    const float* cw   = (const float*)d_in[10];
    const float* cb   = (const float*)d_in[11];
    float* out = (float*)d_out;
    int dup = (out_size >= 2*OUTN) ? 1 : 0;

    void* p;
    cudaGetSymbolAddress(&p, g_zinb);   bf16* zinb = (bf16*)p;
    cudaGetSymbolAddress(&p, g_zb);     bf16* zb   = (bf16*)p;
    cudaGetSymbolAddress(&p, g_G1);     float* G1  = (float*)p;
    cudaGetSymbolAddress(&p, g_Hwb);    bf16* Hwb  = (bf16*)p;
    cudaGetSymbolAddress(&p, g_H2);     float* H2  = (float*)p;
    cudaGetSymbolAddress(&p, g_encb);   bf16* encb = (bf16*)p;
    cudaGetSymbolAddress(&p, g_cwb);    bf16* cwb  = (bf16*)p;
    cudaGetSymbolAddress(&p, g_wihb);   bf16* wihb = (bf16*)p;
    cudaGetSymbolAddress(&p, g_whh_bf); bf16* whhb = (bf16*)p;
    cudaGetSymbolAddress(&p, g_lwb);    bf16* lwb  = (bf16*)p;

    static int attr_done = 0;
    if (!attr_done){
        cudaFuncSetAttribute(k_chain,  cudaFuncAttributeMaxDynamicSharedMemorySize, CH_SMEM);
        cudaFuncSetAttribute(k_logits, cudaFuncAttributeMaxDynamicSharedMemorySize, LG_SMEM);
        attr_done = 1;
    }

    // conversions
    k_f2bf<<<(MROWS*ENCD/4 + 255)/256, 256>>>(enc, encb, MROWS*ENCD);
    k_f2bf<<<(RNNH*ZK/4 + 255)/256, 256>>>(cw, cwb, RNNH*ZK);
    k_f2bf<<<(GATES*RNNH/4 + 255)/256, 256>>>(w_ih, wihb, GATES*RNNH);
    k_f2bf<<<(GATES*RNNH/4 + 255)/256, 256>>>(w_hh, whhb, GATES*RNNH);
    k_f2bf<<<(LABEL*768/4 + 255)/256, 256>>>(lw, lwb, LABEL*768);

    k_scan_meta<<<1, 64>>>(bnd);
    k_build_zin<<<dim3(5, BATCH), 128>>>(enc, bnd, pos, ptab);
    // z = tanh(zin @ combine_w^T + combine_b), t==0 rows zeroed   [bf16 out]
    k_gemm_mma<0><<<dim3(RNNH/128, MROWS/128), 256>>>(zinb, cwb, nullptr, zb, ZK, RNNH, cb, cb);
    // G1 = z @ w_ih^T + b_ih + b_hh   [fp32 out]
    k_gemm_mma<1><<<dim3(GATES/128, MROWS/128), 256>>>(zb, wihb, G1, nullptr, RNNH, GATES, b_ih, b_hh);
    // sequential per-word carry chain: 64 clusters of 4 CTAs
    k_chain<<<BATCH*4, 256, CH_SMEM>>>();
    // H2 = Hw @ w_hh^T (ragged skip)   [fp32 out]
    k_gemm_mma<2><<<dim3(GATES/128, MROWS/128), 256>>>(Hwb, whhb, H2, nullptr, RNNH, GATES, nullptr, nullptr);
    // parallel per-step LSTM outputs [bf16]
    k_apply<<<MROWS, 256>>>();
    // logits + masking + log_softmax
    k_logits<<<MROWS/128, 256, LG_SMEM>>>(len, out, dup);
}

// round 8
// speedup vs baseline: 5.0544x; 1.3451x over previous
#include <cuda_runtime.h>
#include <cuda_bf16.h>
#include <cstdint>
#include <math.h>

#define BATCH 64
#define TLEN  512
#define RNNH  256
#define ENCD  512
#define ZK    640
#define GATES 1024
#define LABEL 128
#define MROWS (BATCH*TLEN)          /* 32768 */
#define OUTN  (4194304)             /* MROWS*LABEL */

typedef __nv_bfloat16 bf16;

// ---------------- scratch (device globals; no allocation allowed) ----------------
__device__ __align__(16) bf16  g_zinb[(size_t)MROWS*ZK];    // [B*T,640] pe|pool (bf16)
__device__ __align__(16) bf16  g_zb  [(size_t)MROWS*RNNH];  // z (bf16)
__device__ __align__(16) bf16  g_G1b[(size_t)MROWS*GATES];  // z@w_ih^T + b_ih + b_hh (bf16)
__device__ __align__(16) bf16  g_Hwb[(size_t)MROWS*RNNH];   // per-word carry h_j (bf16)
__device__ __align__(16) float g_Cw [(size_t)MROWS*RNNH];   // per-word carry c_j (fp32)
__device__ __align__(16) bf16  g_H2b[(size_t)MROWS*GATES];  // Hw@w_hh^T (bf16)
__device__ __align__(16) bf16  g_hsb[(size_t)MROWS*RNNH];   // per-step LSTM output (bf16)
__device__ __align__(16) bf16  g_encb[(size_t)MROWS*ENCD];  // encoder_out bf16
__device__ __align__(16) bf16  g_cwb [RNNH*ZK];
__device__ __align__(16) bf16  g_wihb[GATES*RNNH];
__device__ __align__(16) bf16  g_whh_bf[GATES*RNNH];
__device__ __align__(16) bf16  g_lwb [LABEL*768];
__device__ int   g_svec[MROWS];
__device__ int   g_cidx[MROWS];
__device__ int   g_bpos[MROWS];
__device__ int   g_wcnt[BATCH];

__device__ __forceinline__ float sigf(float x){ return 1.f/(1.f+expf(-x)); }

// ---------------- f32 -> bf16 conversion ----------------------------------------
__global__ void k_f2bf(const float* __restrict__ src, bf16* __restrict__ dst, int n){
    int i = (blockIdx.x*blockDim.x + threadIdx.x)*4;
    if (i < n){
        float4 v = *(const float4*)(src + i);
        __nv_bfloat162* d = (__nv_bfloat162*)(dst + i);
        d[0] = __floats2bfloat162_rn(v.x, v.y);
        d[1] = __floats2bfloat162_rn(v.z, v.w);
    }
}

// ---------------- K0: per-batch boundary scan metadata ---------------------------
__global__ void k_scan_meta(const int* __restrict__ bnd){
    int b = threadIdx.x;
    if (b >= BATCH) return;
    int last = 0, cnt = 0;
    for (int t = 0; t < TLEN; t++){
        g_svec[b*TLEN+t] = last;
        g_cidx[b*TLEN+t] = cnt - 1;
        if (bnd[b*TLEN+t] == 1){ g_bpos[b*TLEN+cnt] = t; cnt++; last = t; }
    }
    g_wcnt[b] = cnt;
}

// ---------------- K1: build zin = [pos_emb(128) | running word mean(512)] --------
__global__ void k_build_zin(const float* __restrict__ enc, const int* __restrict__ bnd,
                            const int* __restrict__ pos, const float* __restrict__ ptab){
    int b = blockIdx.y;
    int chunk = blockIdx.x;       // 0: pe, 1..4: pool dim chunks of 128
    int tid = threadIdx.x;        // 128 threads
    if (chunk == 0){
        for (int t = 0; t < TLEN; t++){
            int s = g_svec[b*TLEN+t];
            int p = pos[b*TLEN+s];
            g_zinb[((size_t)(b*TLEN+t))*ZK + tid] = __float2bfloat16(ptab[p*128 + tid]);
        }
    } else {
        int dim = (chunk-1)*128 + tid;
        float acc = 0.f;
        for (int t = 0; t < TLEN; t++){
            int s = g_svec[b*TLEN+t];
            float wl = (float)((t - s) > 1 ? (t - s) : 1);
            g_zinb[((size_t)(b*TLEN+t))*ZK + 128 + dim] = __float2bfloat16(acc / wl);
            float x = enc[((size_t)(b*TLEN+t))*ENCD + dim];
            acc = (bnd[b*TLEN+t] == 1) ? x : (acc + x);
        }
    }
}

// ================= bf16 tensor-core GEMM: C[M,N] = A[M,K] @ W[N,K]^T ==============
// BM=128, BN=128, BK=32, 256 threads (8 warps as 4x2), warp tile 32x64.
// EPI 0: Cb = bf16(tanh(acc + bias1[n])), zero rows with (m%512)==0
// EPI 1: Cb = bf16(acc + bias1[n] + bias2[n])
// EPI 2: Cb = bf16(acc), skip row tiles fully past word count
#define SSTR 40  /* smem row stride in bf16 elems (80B, conflict-free for ldmatrix) */

__device__ __forceinline__ void ldm_x4(unsigned addr, unsigned& r0, unsigned& r1,
                                       unsigned& r2, unsigned& r3){
    asm volatile("ldmatrix.sync.aligned.m8n8.x4.shared.b16 {%0,%1,%2,%3}, [%4];"
                 : "=r"(r0), "=r"(r1), "=r"(r2), "=r"(r3) : "r"(addr));
}
__device__ __forceinline__ void mma16816(float* c, const unsigned* a, const unsigned* b){
    asm volatile("mma.sync.aligned.m16n8k16.row.col.f32.bf16.bf16.f32 "
                 "{%0,%1,%2,%3}, {%4,%5,%6,%7}, {%8,%9}, {%0,%1,%2,%3};"
                 : "+f"(c[0]), "+f"(c[1]), "+f"(c[2]), "+f"(c[3])
                 : "r"(a[0]), "r"(a[1]), "r"(a[2]), "r"(a[3]), "r"(b[0]), "r"(b[1]));
}

template<int EPI>
__global__ void __launch_bounds__(256) k_gemm_mma(
        const bf16* __restrict__ A, const bf16* __restrict__ W,
        bf16* __restrict__ Cb, int K, int N,
        const float* __restrict__ bias1, const float* __restrict__ bias2){
    int row0 = blockIdx.y * 128;
    int col0 = blockIdx.x * 128;
    if (EPI == 2){
        int b = row0 >> 9;
        if ((row0 & 511) >= g_wcnt[b]) return;
    }
    __shared__ bf16 sA[128*SSTR];
    __shared__ bf16 sW[128*SSTR];
    int tid = threadIdx.x;
    int lane = tid & 31, wid = tid >> 5;
    int warp_m = wid & 3, warp_n = wid >> 2;
    int lrow = tid >> 2, lseg = tid & 3;

    const bf16* Ap = A + (size_t)(row0 + lrow)*K + lseg*8;
    const bf16* Wp = W + (size_t)(col0 + lrow)*K + lseg*8;

    unsigned sAb = (unsigned)__cvta_generic_to_shared(sA);
    unsigned sWb = (unsigned)__cvta_generic_to_shared(sW);
    unsigned aAddr = sAb + (unsigned)(((warp_m*32 + (lane&15))*SSTR + (lane>>4)*8)*2);
    unsigned bAddr = sWb + (unsigned)(((warp_n*64 + ((lane>>4)<<3) + (lane&7))*SSTR
                                      + ((lane>>3)&1)*8)*2);
    float acc[2][8][4];
    #pragma unroll
    for (int mi=0;mi<2;mi++)
        #pragma unroll
        for (int j=0;j<8;j++)
            #pragma unroll
            for (int q=0;q<4;q++) acc[mi][j][q] = 0.f;

    // register prefetch of first tile
    uint4 a0 = *(const uint4*)(Ap);
    uint4 a1 = *(const uint4*)(Ap + (size_t)64*K);
    uint4 w0 = *(const uint4*)(Wp);
    uint4 w1 = *(const uint4*)(Wp + (size_t)64*K);

    for (int k0 = 0; k0 < K; k0 += 32){
        *(uint4*)&sA[lrow*SSTR + lseg*8]       = a0;
        *(uint4*)&sA[(lrow+64)*SSTR + lseg*8]  = a1;
        *(uint4*)&sW[lrow*SSTR + lseg*8]       = w0;
        *(uint4*)&sW[(lrow+64)*SSTR + lseg*8]  = w1;
        __syncthreads();
        // issue next tile's loads before compute (latency overlap)
        if (k0 + 32 < K){
            a0 = *(const uint4*)(Ap + k0 + 32);
            a1 = *(const uint4*)(Ap + (size_t)64*K + k0 + 32);
            w0 = *(const uint4*)(Wp + k0 + 32);
            w1 = *(const uint4*)(Wp + (size_t)64*K + k0 + 32);
        }
        #pragma unroll
        for (int ks = 0; ks < 32; ks += 16){
            unsigned af[2][4], bfg[4][4];
            #pragma unroll
            for (int mi=0;mi<2;mi++)
                ldm_x4(aAddr + mi*16*SSTR*2 + ks*2, af[mi][0],af[mi][1],af[mi][2],af[mi][3]);
            #pragma unroll
            for (int p=0;p<4;p++)
                ldm_x4(bAddr + p*16*SSTR*2 + ks*2, bfg[p][0],bfg[p][1],bfg[p][2],bfg[p][3]);
            #pragma unroll
            for (int mi=0;mi<2;mi++)
                #pragma unroll
                for (int j=0;j<8;j++)
                    mma16816(acc[mi][j], af[mi], &bfg[j>>1][(j&1)*2]);
        }
        __syncthreads();
    }
    // epilogue (bf16 outputs for all EPIs)
    #pragma unroll
    for (int mi=0;mi<2;mi++){
        #pragma unroll
        for (int j=0;j<8;j++){
            #pragma unroll
            for (int q=0;q<2;q++){
                int m = row0 + warp_m*32 + mi*16 + q*8 + (lane>>2);
                int n = col0 + warp_n*64 + j*8 + (lane&3)*2;
                float v0 = acc[mi][j][q*2+0];
                float v1 = acc[mi][j][q*2+1];
                if (EPI == 0){
                    v0 = tanhf(v0 + bias1[n]);
                    v1 = tanhf(v1 + bias1[n+1]);
                    if ((m & 511) == 0){ v0 = 0.f; v1 = 0.f; }
                } else if (EPI == 1){
                    v0 += bias1[n]   + bias2[n];
                    v1 += bias1[n+1] + bias2[n+1];
                }
                *(__nv_bfloat162*)&Cb[(size_t)m*N + n] = __floats2bfloat162_rn(v0, v1);
            }
        }
    }
}

// ---------------- K4: cluster-4 chain, 2 batches/cluster, HFMA2 matvec -----------
// 32 clusters x 4 CTAs (single wave). Rank r owns gate chunk r (256 rows of w_hh).
// Weights in smem as uint4 of 4 bf16x2 K-pairs, layout [cb][row], padded stride.
// Per step: dual-batch bf16x2 matvec (weight LDS shared across batches), gates
// packed (b0,b1) into one b32 DSMEM store to all 4 ranks, one cluster barrier,
// redundant fp32 cell update for both batches, h repacked to bf16x2.
#define CSTR 257
#define CH_SMEM (32*CSTR*16 + 2048 + 2048 + 1024 + 8192)
extern __shared__ char chsm[];

__global__ void __cluster_dims__(4,1,1) __launch_bounds__(256, 1) k_chain(){
    uint4* sw4  = (uint4*)chsm;                       // [32][CSTR] (cb-major)
    float* sh_c  = (float*)(chsm + 32*CSTR*16);       // [2][256] fp32 cell
    float* sh_hf = sh_c + 512;                        // [2][256] fp32 hidden
    uint4* sh_h2 = (uint4*)(sh_hf + 512);             // [2][32] = h as bf16x2 packs
    __nv_bfloat162* gbuf = (__nv_bfloat162*)((char*)sh_h2 + 1024); // [2][1024]
    int tid = threadIdx.x;                            // 256
    unsigned int r; asm("mov.u32 %0, %%cluster_ctarank;" : "=r"(r));
    int c = blockIdx.x >> 2;
    int b0 = 2*c, b1 = 2*c + 1;

    // stage weight rows [r*256, r*256+256): sw4[cb*CSTR + row] = row-chunk cb
    const uint4* wg = (const uint4*)&g_whh_bf[((size_t)r*256)*256];  // 32 uint4/row
    for (int idx = tid; idx < 256*32; idx += 256){
        int row = idx >> 5, cb = idx & 31;
        sw4[cb*CSTR + row] = wg[row*32 + cb];
    }
    sh_c[tid] = 0.f;  sh_c[256+tid] = 0.f;
    sh_hf[tid] = 0.f; sh_hf[256+tid] = 0.f;
    if (tid < 64) sh_h2[tid] = make_uint4(0,0,0,0);
    __syncthreads();

    int W0 = g_wcnt[b0], W1 = g_wcnt[b1];
    int Wmax = (W0 > W1) ? W0 : W1;

    unsigned int l0 = (unsigned int)__cvta_generic_to_shared(&gbuf[r*256 + tid]);
    unsigned int peer[4];
    #pragma unroll
    for (int q = 0; q < 4; q++)
        asm("mapa.shared::cluster.u32 %0, %1, %2;" : "=r"(peer[q]) : "r"(l0), "r"(q));

    const bf16* g1p0 = &g_G1b[((size_t)b0*TLEN)*GATES + r*256 + tid];
    const bf16* g1p1 = &g_G1b[((size_t)b1*TLEN)*GATES + r*256 + tid];
    unsigned int p = 0;
    for (int k = 0; k < Wmax; k++){
        int t0 = (k < W0) ? g_bpos[b0*TLEN + k] : 0;
        int t1 = (k < W1) ? g_bpos[b1*TLEN + k] : 0;
        float g10 = __bfloat162float(g1p0[(size_t)t0*GATES]);
        float g11 = __bfloat162float(g1p1[(size_t)t1*GATES]);
        __nv_bfloat162 zz = __floats2bfloat162_rn(0.f, 0.f);
        __nv_bfloat162 a0a = zz, a0b = zz, a1a = zz, a1b = zz;
        #pragma unroll 8
        for (int cb = 0; cb < 32; cb++){
            uint4 w  = sw4[cb*CSTR + tid];
            uint4 h0 = sh_h2[cb];
            uint4 h1 = sh_h2[32 + cb];
            const __nv_bfloat162* wp  = (const __nv_bfloat162*)&w;
            const __nv_bfloat162* hp0 = (const __nv_bfloat162*)&h0;
            const __nv_bfloat162* hp1 = (const __nv_bfloat162*)&h1;
            a0a = __hfma2(wp[0], hp0[0], a0a); a0b = __hfma2(wp[1], hp0[1], a0b);
            a0a = __hfma2(wp[2], hp0[2], a0a); a0b = __hfma2(wp[3], hp0[3], a0b);
            a1a = __hfma2(wp[0], hp1[0], a1a); a1b = __hfma2(wp[1], hp1[1], a1b);
            a1a = __hfma2(wp[2], hp1[2], a1a); a1b = __hfma2(wp[3], hp1[3], a1b);
        }
        float2 f0a = __bfloat1622float2(a0a), f0b = __bfloat1622float2(a0b);
        float2 f1a = __bfloat1622float2(a1a), f1b = __bfloat1622float2(a1b);
        float s0 = (f0a.x + f0a.y) + (f0b.x + f0b.y);
        float s1 = (f1a.x + f1a.y) + (f1b.x + f1b.y);
        __nv_bfloat162 gate2 = __floats2bfloat162_rn(g10 + s0, g11 + s1);
        unsigned int gv; { __nv_bfloat162 tmp = gate2; gv = *(unsigned int*)&tmp; }
        unsigned int poff = p * 4096u;  // parity stride (1024 x 4B)
        #pragma unroll
        for (int q = 0; q < 4; q++)
            asm volatile("st.shared::cluster.b32 [%0], %1;"
                         :: "r"(peer[q] + poff), "r"(gv) : "memory");
        asm volatile("barrier.cluster.arrive.aligned;" ::: "memory");
        asm volatile("barrier.cluster.wait.aligned;"   ::: "memory");
        const __nv_bfloat162* gb = gbuf + p*1024;
        float2 iv = __bfloat1622float2(gb[tid]);
        float2 fv = __bfloat1622float2(gb[256+tid]);
        float2 gg = __bfloat1622float2(gb[512+tid]);
        float2 ov = __bfloat1622float2(gb[768+tid]);
        if (k < W0){
            float cc = sigf(fv.x)*sh_c[tid] + sigf(iv.x)*tanhf(gg.x);
            float hh = sigf(ov.x)*tanhf(cc);
            sh_c[tid] = cc; sh_hf[tid] = hh;
            if (r == 0) g_Hwb[((size_t)(b0*TLEN + k))*RNNH + tid] = __float2bfloat16(hh);
            if (r == 1) g_Cw [((size_t)(b0*TLEN + k))*RNNH + tid] = cc;
        }
        if (k < W1){
            float cc = sigf(fv.y)*sh_c[256+tid] + sigf(iv.y)*tanhf(gg.y);
            float hh = sigf(ov.y)*tanhf(cc);
            sh_c[256+tid] = cc; sh_hf[256+tid] = hh;
            if (r == 0) g_Hwb[((size_t)(b1*TLEN + k))*RNNH + tid] = __float2bfloat16(hh);
            if (r == 1) g_Cw [((size_t)(b1*TLEN + k))*RNNH + tid] = cc;
        }
        __syncthreads();
        // repack h into bf16x2: threads 0..127 -> b0, 128..255 -> b1
        {
            int bb = tid >> 7, i = tid & 127;
            float x = sh_hf[bb*256 + 2*i], y = sh_hf[bb*256 + 2*i + 1];
            ((__nv_bfloat162*)sh_h2)[bb*128 + i] = __floats2bfloat162_rn(x, y);
        }
        p ^= 1;
        __syncthreads();
    }
    asm volatile("barrier.cluster.arrive.aligned;" ::: "memory");
    asm volatile("barrier.cluster.wait.aligned;"   ::: "memory");
}

// ---------------- K5: parallel per-step LSTM cell apply --------------------------
__global__ void k_apply(){
    int m = blockIdx.x;
    int d = threadIdx.x;          // 256
    int b = m >> 9;
    int j = g_cidx[m];
    size_t gbase = (size_t)m*GATES;
    float iv = __bfloat162float(g_G1b[gbase +       d]);
    float fv = __bfloat162float(g_G1b[gbase + 256 + d]);
    float gv = __bfloat162float(g_G1b[gbase + 512 + d]);
    float ov = __bfloat162float(g_G1b[gbase + 768 + d]);
    float cprev = 0.f;
    if (j >= 0){
        size_t hbase = (size_t)(b*TLEN + j)*GATES;
        iv += __bfloat162float(g_H2b[hbase +       d]);
        fv += __bfloat162float(g_H2b[hbase + 256 + d]);
        gv += __bfloat162float(g_H2b[hbase + 512 + d]);
        ov += __bfloat162float(g_H2b[hbase + 768 + d]);
        cprev = g_Cw[(size_t)(b*TLEN + j)*RNNH + d];
    }
    float cc = sigf(fv)*cprev + sigf(iv)*tanhf(gv);
    g_hsb[(size_t)m*RNNH + d] = __float2bfloat16(sigf(ov)*tanhf(cc));
}

// ---------------- K6: logits mma GEMM ([hs|enc] @ lw^T) + fused log_softmax ------
#define LG_SMEM (128*132*4)
__global__ void __launch_bounds__(256) k_logits(const int* __restrict__ lengths,
                                                float* __restrict__ out, int dup){
    __shared__ bf16 sA[128*SSTR];
    __shared__ bf16 sW[128*SSTR];
    float* sC = (float*)chsm;    // [128][132]
    int row0 = blockIdx.x * 128;
    int tid = threadIdx.x;
    int lane = tid & 31, wid = tid >> 5;
    int warp_m = wid & 3, warp_n = wid >> 2;
    int lrow = tid >> 2, lseg = tid & 3;

    unsigned sAb = (unsigned)__cvta_generic_to_shared(sA);
    unsigned sWb = (unsigned)__cvta_generic_to_shared(sW);
    unsigned aAddr = sAb + (unsigned)(((warp_m*32 + (lane&15))*SSTR + (lane>>4)*8)*2);
    unsigned bAddr = sWb + (unsigned)(((warp_n*64 + ((lane>>4)<<3) + (lane&7))*SSTR
                                      + ((lane>>3)&1)*8)*2);
    float acc[2][8][4];
    #pragma unroll
    for (int mi=0;mi<2;mi++)
        #pragma unroll
        for (int j=0;j<8;j++)
            #pragma unroll
            for (int q=0;q<4;q++) acc[mi][j][q] = 0.f;

    for (int k0 = 0; k0 < 768; k0 += 32){
        int kk = k0 + lseg*8;
        int m0 = row0 + lrow;
        uint4 a0, a1;
        if (kk < 256){
            a0 = *(const uint4*)&g_hsb[(size_t)m0*RNNH + kk];
            a1 = *(const uint4*)&g_hsb[(size_t)(m0+64)*RNNH + kk];
        } else {
            a0 = *(const uint4*)&g_encb[(size_t)m0*ENCD + kk - 256];
            a1 = *(const uint4*)&g_encb[(size_t)(m0+64)*ENCD + kk - 256];
        }
        uint4 w0 = *(const uint4*)&g_lwb[(size_t)lrow*768 + kk];
        uint4 w1 = *(const uint4*)&g_lwb[(size_t)(lrow+64)*768 + kk];
        *(uint4*)&sA[lrow*SSTR + lseg*8]      = a0;
        *(uint4*)&sA[(lrow+64)*SSTR + lseg*8] = a1;
        *(uint4*)&sW[lrow*SSTR + lseg*8]      = w0;
        *(uint4*)&sW[(lrow+64)*SSTR + lseg*8] = w1;
        __syncthreads();
        #pragma unroll
        for (int ks = 0; ks < 32; ks += 16){
            unsigned af[2][4], bfg[4][4];
            #pragma unroll
            for (int mi=0;mi<2;mi++)
                ldm_x4(aAddr + mi*16*SSTR*2 + ks*2, af[mi][0],af[mi][1],af[mi][2],af[mi][3]);
            #pragma unroll
            for (int p=0;p<4;p++)
                ldm_x4(bAddr + p*16*SSTR*2 + ks*2, bfg[p][0],bfg[p][1],bfg[p][2],bfg[p][3]);
            #pragma unroll
            for (int mi=0;mi<2;mi++)
                #pragma unroll
                for (int j=0;j<8;j++)
                    mma16816(acc[mi][j], af[mi], &bfg[j>>1][(j&1)*2]);
        }
        __syncthreads();
    }
    // stage logits tile in smem
    #pragma unroll
    for (int mi=0;mi<2;mi++)
        #pragma unroll
        for (int j=0;j<8;j++)
            #pragma unroll
            for (int q=0;q<2;q++){
                int rl = warp_m*32 + mi*16 + q*8 + (lane>>2);
                int cl = warp_n*64 + j*8 + (lane&3)*2;
                *(float2*)&sC[rl*132 + cl] = make_float2(acc[mi][j][q*2], acc[mi][j][q*2+1]);
            }
    __syncthreads();
    // per-row log_softmax
    for (int rr = 0; rr < 16; rr++){
        int rl = wid*16 + rr;
        int m = row0 + rl;
        int b = m >> 9, t = m & 511;
        int L = lengths[b];
        float v[4];
        float vmax = -3.0e38f;
        #pragma unroll
        for (int u=0;u<4;u++){
            int n = lane + u*32;
            float x = sC[rl*132 + n];
            if (t == 0 && n == 0) x = -1e30f;
            if (t >= L) x = 0.f;
            v[u] = x;
            vmax = fmaxf(vmax, x);
        }
        #pragma unroll
        for (int d=16; d>=1; d>>=1) vmax = fmaxf(vmax, __shfl_xor_sync(0xffffffffu, vmax, d, 32));
        float ssum = 0.f;
        #pragma unroll
        for (int u=0;u<4;u++) ssum += expf(v[u] - vmax);
        #pragma unroll
        for (int d=16; d>=1; d>>=1) ssum += __shfl_xor_sync(0xffffffffu, ssum, d, 32);
        float lse = vmax + logf(ssum);
        #pragma unroll
        for (int u=0;u<4;u++){
            int n = lane + u*32;
            size_t idx = (size_t)m*LABEL + n;
            float r = v[u] - lse;
            out[idx] = r;
            if (dup) out[(size_t)OUTN + idx] = r;
        }
    }
}

// ---------------- launcher -------------------------------------------------------
extern "C" void kernel_launch(void* const* d_in, const int* in_sizes, int n_in,
                              void* d_out, int out_size){
    const float* enc  = (const float*)d_in[0];
    const int*   bnd  = (const int*)  d_in[1];
    const int*   pos  = (const int*)  d_in[2];
    const int*   len  = (const int*)  d_in[3];
    const float* w_ih = (const float*)d_in[4];
    const float* w_hh = (const float*)d_in[5];
    const float* b_ih = (const float*)d_in[6];
    const float* b_hh = (const float*)d_in[7];
    const float* ptab = (const float*)d_in[8];
    const float* lw   = (const float*)d_in[9];
    const float* cw   = (const float*)d_in[10];
    const float* cb   = (const float*)d_in[11];
    float* out = (float*)d_out;
    int dup = (out_size >= 2*OUTN) ? 1 : 0;

    void* p;
    cudaGetSymbolAddress(&p, g_zinb);   bf16* zinb = (bf16*)p;
    cudaGetSymbolAddress(&p, g_zb);     bf16* zb   = (bf16*)p;
    cudaGetSymbolAddress(&p, g_G1b);    bf16* G1b  = (bf16*)p;
    cudaGetSymbolAddress(&p, g_Hwb);    bf16* Hwb  = (bf16*)p;
    cudaGetSymbolAddress(&p, g_H2b);    bf16* H2b  = (bf16*)p;
    cudaGetSymbolAddress(&p, g_encb);   bf16* encb = (bf16*)p;
    cudaGetSymbolAddress(&p, g_cwb);    bf16* cwb  = (bf16*)p;
    cudaGetSymbolAddress(&p, g_wihb);   bf16* wihb = (bf16*)p;
    cudaGetSymbolAddress(&p, g_whh_bf); bf16* whhb = (bf16*)p;
    cudaGetSymbolAddress(&p, g_lwb);    bf16* lwb  = (bf16*)p;

    static int attr_done = 0;
    if (!attr_done){
        cudaFuncSetAttribute(k_chain,  cudaFuncAttributeMaxDynamicSharedMemorySize, CH_SMEM);
        cudaFuncSetAttribute(k_logits, cudaFuncAttributeMaxDynamicSharedMemorySize, LG_SMEM);
        attr_done = 1;
    }

    // conversions
    k_f2bf<<<(MROWS*ENCD/4 + 255)/256, 256>>>(enc, encb, MROWS*ENCD);
    k_f2bf<<<(RNNH*ZK/4 + 255)/256, 256>>>(cw, cwb, RNNH*ZK);
    k_f2bf<<<(GATES*RNNH/4 + 255)/256, 256>>>(w_ih, wihb, GATES*RNNH);
    k_f2bf<<<(GATES*RNNH/4 + 255)/256, 256>>>(w_hh, whhb, GATES*RNNH);
    k_f2bf<<<(LABEL*768/4 + 255)/256, 256>>>(lw, lwb, LABEL*768);

    k_scan_meta<<<1, 64>>>(bnd);
    k_build_zin<<<dim3(5, BATCH), 128>>>(enc, bnd, pos, ptab);
    // z = tanh(zin @ combine_w^T + combine_b), t==0 rows zeroed   [bf16 out]
    k_gemm_mma<0><<<dim3(RNNH/128, MROWS/128), 256>>>(zinb, cwb, zb, ZK, RNNH, cb, cb);
    // G1 = z @ w_ih^T + b_ih + b_hh   [bf16 out]
    k_gemm_mma<1><<<dim3(GATES/128, MROWS/128), 256>>>(zb, wihb, G1b, RNNH, GATES, b_ih, b_hh);
    // sequential per-word carry chain: 32 clusters of 4 CTAs, 2 batches each
    k_chain<<<(BATCH/2)*4, 256, CH_SMEM>>>();
    // H2 = Hw @ w_hh^T (ragged skip)   [bf16 out]
    k_gemm_mma<2><<<dim3(GATES/128, MROWS/128), 256>>>(Hwb, whhb, H2b, RNNH, GATES, nullptr, nullptr);
    // parallel per-step LSTM outputs [bf16]
    k_apply<<<MROWS, 256>>>();
    // logits + masking + log_softmax
    k_logits<<<MROWS/128, 256, LG_SMEM>>>(len, out, dup);
}

// round 9
// speedup vs baseline: 6.1001x; 1.2069x over previous
#include <cuda_runtime.h>
#include <cuda_bf16.h>
#include <cstdint>
#include <math.h>

#define BATCH 64
#define TLEN  512
#define RNNH  256
#define ENCD  512
#define ZK    640
#define GATES 1024
#define LABEL 128
#define MROWS (BATCH*TLEN)          /* 32768 */
#define OUTN  (4194304)             /* MROWS*LABEL */

typedef __nv_bfloat16 bf16;

// ---------------- scratch (device globals; no allocation allowed) ----------------
__device__ __align__(16) bf16  g_zinb[(size_t)MROWS*ZK];    // [B*T,640] pe|pool (bf16)
__device__ __align__(16) bf16  g_zb  [(size_t)MROWS*RNNH];  // z (bf16)
__device__ __align__(16) bf16  g_G1b[(size_t)MROWS*GATES];  // z@w_ih^T + b_ih + b_hh (bf16)
__device__ __align__(16) bf16  g_Hwb[(size_t)MROWS*RNNH];   // per-word carry h_j (bf16)
__device__ __align__(16) float g_Cw [(size_t)MROWS*RNNH];   // per-word carry c_j (fp32)
__device__ __align__(16) bf16  g_H2b[(size_t)MROWS*GATES];  // Hw@w_hh^T (bf16)
__device__ __align__(16) bf16  g_hsb[(size_t)MROWS*RNNH];   // per-step LSTM output (bf16)
__device__ __align__(16) bf16  g_encb[(size_t)MROWS*ENCD];  // encoder_out bf16
__device__ __align__(16) bf16  g_cwb [RNNH*ZK];
__device__ __align__(16) bf16  g_wihb[GATES*RNNH];
__device__ __align__(16) bf16  g_whh_bf[GATES*RNNH];
__device__ __align__(16) bf16  g_lwb [LABEL*768];
__device__ int   g_svec[MROWS];
__device__ int   g_cidx[MROWS];
__device__ int   g_bpos[MROWS];
__device__ int   g_wcnt[BATCH];

__device__ __forceinline__ float sigf(float x){ return 1.f/(1.f+expf(-x)); }

// ---------------- K-1: all f32->bf16 conversions in ONE launch -------------------
#define N_ENC4 (MROWS*ENCD/4)
#define N_CW4  (RNNH*ZK/4)
#define N_W4   (GATES*RNNH/4)
#define N_LW4  (LABEL*768/4)
#define N_ALL4 (N_ENC4 + N_CW4 + N_W4 + N_W4 + N_LW4)

__device__ __forceinline__ void cvt4(const float* s, bf16* d, long i){
    float4 v = *(const float4*)(s + i*4);
    __nv_bfloat162* o = (__nv_bfloat162*)(d + i*4);
    o[0] = __floats2bfloat162_rn(v.x, v.y);
    o[1] = __floats2bfloat162_rn(v.z, v.w);
}
__global__ void k_convert_all(const float* __restrict__ enc, const float* __restrict__ cw,
                              const float* __restrict__ wih, const float* __restrict__ whh,
                              const float* __restrict__ lw){
    long i = (long)blockIdx.x*blockDim.x + threadIdx.x;
    if (i < N_ENC4){ cvt4(enc, g_encb, i); return; }
    i -= N_ENC4;
    if (i < N_CW4){ cvt4(cw, g_cwb, i); return; }
    i -= N_CW4;
    if (i < N_W4){ cvt4(wih, g_wihb, i); return; }
    i -= N_W4;
    if (i < N_W4){ cvt4(whh, g_whh_bf, i); return; }
    i -= N_W4;
    if (i < N_LW4){ cvt4(lw, g_lwb, i); }
}

// ---------------- K0: boundary scan metadata via warp ballot ---------------------
__global__ void k_scan_meta(const int* __restrict__ bnd){
    int warp = (blockIdx.x*blockDim.x + threadIdx.x) >> 5;
    int lane = threadIdx.x & 31;
    if (warp >= BATCH) return;
    int base = warp*TLEN;
    int cnt = 0, last = 0;
    for (int c = 0; c < TLEN/32; c++){
        int t = c*32 + lane;
        int bv = bnd[base + t];
        unsigned m = __ballot_sync(0xffffffffu, bv == 1);
        unsigned mlt = m & ((1u << lane) - 1u);
        int sv = mlt ? (c*32 + 31 - __clz(mlt)) : last;
        g_svec[base + t] = sv;
        g_cidx[base + t] = cnt + __popc(mlt) - 1;
        if (bv == 1) g_bpos[base + cnt + __popc(mlt)] = t;
        cnt += __popc(m);
        last = m ? (c*32 + 31 - __clz(m)) : last;
    }
    if (lane == 0) g_wcnt[warp] = cnt;
}

// ---------------- K1: build zin = [pos_emb(128) | running word mean(512)] --------
__global__ void k_build_zin(const float* __restrict__ enc, const int* __restrict__ bnd,
                            const int* __restrict__ pos, const float* __restrict__ ptab){
    int b = blockIdx.y;
    int chunk = blockIdx.x;       // 0: pe, 1..4: pool dim chunks of 128
    int tid = threadIdx.x;        // 128 threads
    if (chunk == 0){
        for (int t = 0; t < TLEN; t++){
            int s = g_svec[b*TLEN+t];
            int p = pos[b*TLEN+s];
            g_zinb[((size_t)(b*TLEN+t))*ZK + tid] = __float2bfloat16(ptab[p*128 + tid]);
        }
    } else {
        int dim = (chunk-1)*128 + tid;
        float acc = 0.f;
        for (int t = 0; t < TLEN; t++){
            int s = g_svec[b*TLEN+t];
            float wl = (float)((t - s) > 1 ? (t - s) : 1);
            g_zinb[((size_t)(b*TLEN+t))*ZK + 128 + dim] = __float2bfloat16(acc / wl);
            float x = enc[((size_t)(b*TLEN+t))*ENCD + dim];
            acc = (bnd[b*TLEN+t] == 1) ? x : (acc + x);
        }
    }
}

// ================= bf16 tensor-core GEMM: C[M,N] = A[M,K] @ W[N,K]^T ==============
#define SSTR 40  /* smem row stride in bf16 elems (80B, conflict-free for ldmatrix) */

__device__ __forceinline__ void ldm_x4(unsigned addr, unsigned& r0, unsigned& r1,
                                       unsigned& r2, unsigned& r3){
    asm volatile("ldmatrix.sync.aligned.m8n8.x4.shared.b16 {%0,%1,%2,%3}, [%4];"
                 : "=r"(r0), "=r"(r1), "=r"(r2), "=r"(r3) : "r"(addr));
}
__device__ __forceinline__ void mma16816(float* c, const unsigned* a, const unsigned* b){
    asm volatile("mma.sync.aligned.m16n8k16.row.col.f32.bf16.bf16.f32 "
                 "{%0,%1,%2,%3}, {%4,%5,%6,%7}, {%8,%9}, {%0,%1,%2,%3};"
                 : "+f"(c[0]), "+f"(c[1]), "+f"(c[2]), "+f"(c[3])
                 : "r"(a[0]), "r"(a[1]), "r"(a[2]), "r"(a[3]), "r"(b[0]), "r"(b[1]));
}

template<int EPI>
__global__ void __launch_bounds__(256) k_gemm_mma(
        const bf16* __restrict__ A, const bf16* __restrict__ W,
        bf16* __restrict__ Cb, int K, int N,
        const float* __restrict__ bias1, const float* __restrict__ bias2){
    int row0 = blockIdx.y * 128;
    int col0 = blockIdx.x * 128;
    if (EPI == 2){
        int b = row0 >> 9;
        if ((row0 & 511) >= g_wcnt[b]) return;
    }
    __shared__ bf16 sA[128*SSTR];
    __shared__ bf16 sW[128*SSTR];
    int tid = threadIdx.x;
    int lane = tid & 31, wid = tid >> 5;
    int warp_m = wid & 3, warp_n = wid >> 2;
    int lrow = tid >> 2, lseg = tid & 3;

    const bf16* Ap = A + (size_t)(row0 + lrow)*K + lseg*8;
    const bf16* Wp = W + (size_t)(col0 + lrow)*K + lseg*8;

    unsigned sAb = (unsigned)__cvta_generic_to_shared(sA);
    unsigned sWb = (unsigned)__cvta_generic_to_shared(sW);
    unsigned aAddr = sAb + (unsigned)(((warp_m*32 + (lane&15))*SSTR + (lane>>4)*8)*2);
    unsigned bAddr = sWb + (unsigned)(((warp_n*64 + ((lane>>4)<<3) + (lane&7))*SSTR
                                      + ((lane>>3)&1)*8)*2);
    float acc[2][8][4];
    #pragma unroll
    for (int mi=0;mi<2;mi++)
        #pragma unroll
        for (int j=0;j<8;j++)
            #pragma unroll
            for (int q=0;q<4;q++) acc[mi][j][q] = 0.f;

    uint4 a0 = *(const uint4*)(Ap);
    uint4 a1 = *(const uint4*)(Ap + (size_t)64*K);
    uint4 w0 = *(const uint4*)(Wp);
    uint4 w1 = *(const uint4*)(Wp + (size_t)64*K);

    for (int k0 = 0; k0 < K; k0 += 32){
        *(uint4*)&sA[lrow*SSTR + lseg*8]       = a0;
        *(uint4*)&sA[(lrow+64)*SSTR + lseg*8]  = a1;
        *(uint4*)&sW[lrow*SSTR + lseg*8]       = w0;
        *(uint4*)&sW[(lrow+64)*SSTR + lseg*8]  = w1;
        __syncthreads();
        if (k0 + 32 < K){
            a0 = *(const uint4*)(Ap + k0 + 32);
            a1 = *(const uint4*)(Ap + (size_t)64*K + k0 + 32);
            w0 = *(const uint4*)(Wp + k0 + 32);
            w1 = *(const uint4*)(Wp + (size_t)64*K + k0 + 32);
        }
        #pragma unroll
        for (int ks = 0; ks < 32; ks += 16){
            unsigned af[2][4], bfg[4][4];
            #pragma unroll
            for (int mi=0;mi<2;mi++)
                ldm_x4(aAddr + mi*16*SSTR*2 + ks*2, af[mi][0],af[mi][1],af[mi][2],af[mi][3]);
            #pragma unroll
            for (int p=0;p<4;p++)
                ldm_x4(bAddr + p*16*SSTR*2 + ks*2, bfg[p][0],bfg[p][1],bfg[p][2],bfg[p][3]);
            #pragma unroll
            for (int mi=0;mi<2;mi++)
                #pragma unroll
                for (int j=0;j<8;j++)
                    mma16816(acc[mi][j], af[mi], &bfg[j>>1][(j&1)*2]);
        }
        __syncthreads();
    }
    #pragma unroll
    for (int mi=0;mi<2;mi++){
        #pragma unroll
        for (int j=0;j<8;j++){
            #pragma unroll
            for (int q=0;q<2;q++){
                int m = row0 + warp_m*32 + mi*16 + q*8 + (lane>>2);
                int n = col0 + warp_n*64 + j*8 + (lane&3)*2;
                float v0 = acc[mi][j][q*2+0];
                float v1 = acc[mi][j][q*2+1];
                if (EPI == 0){
                    v0 = tanhf(v0 + bias1[n]);
                    v1 = tanhf(v1 + bias1[n+1]);
                    if ((m & 511) == 0){ v0 = 0.f; v1 = 0.f; }
                } else if (EPI == 1){
                    v0 += bias1[n]   + bias2[n];
                    v1 += bias1[n+1] + bias2[n+1];
                }
                *(__nv_bfloat162*)&Cb[(size_t)m*N + n] = __floats2bfloat162_rn(v0, v1);
            }
        }
    }
}

// ---------------- K4: cluster-4 chain, h-partitioned, st.async exchange ----------
// 32 clusters x 4 CTAs, 2 batches each. Rank r owns h-elements [64r,64r+64) and
// ALL 4 gate rows for them (rows q*256+64r+e, 256 rows = 128KB bf16 in smem).
// Per step: full-h matvec (h from smem, refreshed by peers via st.async), gates
// staged in parity-doubled sgate, 1 syncthreads, cell update in 128 threads with
// register (c,h), new h bf16x2-packed and st.async-broadcast to all 4 CTAs'
// parity h-buffer + mbarrier complete_tx. Wait = mbarrier try_wait (no
// barrier.cluster on the critical path).
#define CH_SW   0
#define CH_HB   131072                 /* [2 parity][2 batch][512B] = 2048 */
#define CH_SG   (CH_HB + 2048)         /* [2 parity][2 batch][256] fp32 = 4096 */
#define CH_MB   (CH_SG + 4096)         /* 2 mbarriers = 16 (+pad) */
#define CH_SMEM (CH_MB + 64)
#define CH_TXB  1024                   /* bytes per mbar phase: 2x128 words x4B */
extern __shared__ char chsm[];

__device__ __forceinline__ void mbar_wait_cluster(unsigned addr, unsigned parity){
    unsigned done = 0;
    while (!done){
        asm volatile(
            "{\n\t.reg .pred p;\n\t"
            "mbarrier.try_wait.parity.acquire.cluster.shared::cta.b64 p, [%1], %2, 0x989680;\n\t"
            "selp.b32 %0, 1, 0, p;\n\t}"
            : "=r"(done) : "r"(addr), "r"(parity) : "memory");
    }
}

__global__ void __cluster_dims__(4,1,1) __launch_bounds__(256, 1) k_chain(){
    uint4* sw4  = (uint4*)(chsm + CH_SW);            // [32 cb][256 rows]
    uint4* hb4  = (uint4*)(chsm + CH_HB);            // [2p][2b][32 cb]
    float* sg   = (float*)(chsm + CH_SG);            // [2p][2b][256]
    unsigned mb = (unsigned)__cvta_generic_to_shared(chsm + CH_MB);
    unsigned smem_base = (unsigned)__cvta_generic_to_shared(chsm);
    int tid = threadIdx.x;                           // 256
    unsigned r; asm("mov.u32 %0, %%cluster_ctarank;" : "=r"(r));
    int c = blockIdx.x >> 2;
    int b0 = 2*c, b1 = 2*c + 1;

    // stage weight rows: local row l = q*64+e -> global row q*256 + 64r + e
    for (int idx = tid; idx < 256*32; idx += 256){
        int l = idx >> 5, cb = idx & 31;
        int G = (l >> 6)*256 + 64*(int)r + (l & 63);
        sw4[cb*256 + l] = ((const uint4*)&g_whh_bf[(size_t)G*256])[cb];
    }
    // zero both h parity buffers
    if (tid < 128) hb4[tid] = make_uint4(0,0,0,0);
    if (tid == 0){
        asm volatile("mbarrier.init.shared.b64 [%0], %1;" :: "r"(mb),   "r"(1) : "memory");
        asm volatile("mbarrier.init.shared.b64 [%0], %1;" :: "r"(mb+8), "r"(1) : "memory");
        asm volatile("mbarrier.arrive.expect_tx.shared::cta.b64 _, [%0], %1;"
                     :: "r"(mb),   "r"(CH_TXB) : "memory");
        asm volatile("mbarrier.arrive.expect_tx.shared::cta.b64 _, [%0], %1;"
                     :: "r"(mb+8), "r"(CH_TXB) : "memory");
    }
    __syncthreads();
    asm volatile("barrier.cluster.arrive.aligned;" ::: "memory");
    asm volatile("barrier.cluster.wait.aligned;"   ::: "memory");

    int W0 = g_wcnt[b0], W1 = g_wcnt[b1];
    int Wmax = (W0 > W1) ? W0 : W1;

    // peer smem base addresses (cluster-mapped)
    unsigned peer[4];
    #pragma unroll
    for (int q = 0; q < 4; q++)
        asm("mapa.shared::cluster.u32 %0, %1, %2;" : "=r"(peer[q]) : "r"(smem_base), "r"(q));

    int grow = (tid >> 6)*256 + 64*(int)r + (tid & 63);     // global gate row for matvec
    const bf16* g1p0 = &g_G1b[((size_t)b0*TLEN)*GATES + grow];
    const bf16* g1p1 = &g_G1b[((size_t)b1*TLEN)*GATES + grow];
    int cbatch = tid >> 6;        // cell thread batch (tid<128)
    int eloc   = tid & 63;
    float cc = 0.f, hh = 0.f;     // register cell state (cell threads)
    int ph[2] = {0, 0};

    for (int k = 0; k < Wmax; k++){
        int p = k & 1, p2 = p ^ 1;
        if (k > 0){
            mbar_wait_cluster(mb + p*8, (unsigned)ph[p]);
            ph[p] ^= 1;
            if (tid == 0)
                asm volatile("mbarrier.arrive.expect_tx.shared::cta.b64 _, [%0], %1;"
                             :: "r"(mb + p*8), "r"(CH_TXB) : "memory");
        }
        int t0 = (k < W0) ? g_bpos[b0*TLEN + k] : 0;
        int t1 = (k < W1) ? g_bpos[b1*TLEN + k] : 0;
        float g10 = __bfloat162float(g1p0[(size_t)t0*GATES]);
        float g11 = __bfloat162float(g1p1[(size_t)t1*GATES]);
        // matvec: row tid, both batches, h from hb4[p]
        __nv_bfloat162 zz = __floats2bfloat162_rn(0.f, 0.f);
        __nv_bfloat162 a0a = zz, a0b = zz, a1a = zz, a1b = zz;
        const uint4* h0p = &hb4[p*64];
        const uint4* h1p = &hb4[p*64 + 32];
        #pragma unroll 8
        for (int cb = 0; cb < 32; cb++){
            uint4 w  = sw4[cb*256 + tid];
            uint4 h0 = h0p[cb];
            uint4 h1 = h1p[cb];
            const __nv_bfloat162* wp  = (const __nv_bfloat162*)&w;
            const __nv_bfloat162* hp0 = (const __nv_bfloat162*)&h0;
            const __nv_bfloat162* hp1 = (const __nv_bfloat162*)&h1;
            a0a = __hfma2(wp[0], hp0[0], a0a); a0b = __hfma2(wp[1], hp0[1], a0b);
            a0a = __hfma2(wp[2], hp0[2], a0a); a0b = __hfma2(wp[3], hp0[3], a0b);
            a1a = __hfma2(wp[0], hp1[0], a1a); a1b = __hfma2(wp[1], hp1[1], a1b);
            a1a = __hfma2(wp[2], hp1[2], a1a); a1b = __hfma2(wp[3], hp1[3], a1b);
        }
        float2 f0a = __bfloat1622float2(a0a), f0b = __bfloat1622float2(a0b);
        float2 f1a = __bfloat1622float2(a1a), f1b = __bfloat1622float2(a1b);
        sg[p*512 +       tid] = g10 + (f0a.x + f0a.y) + (f0b.x + f0b.y);
        sg[p*512 + 256 + tid] = g11 + (f1a.x + f1a.y) + (f1b.x + f1b.y);
        __syncthreads();
        if (tid < 128){
            const float* s = &sg[p*512 + cbatch*256];
            float iv = s[eloc], fv = s[64+eloc], gv = s[128+eloc], ov = s[192+eloc];
            bool act = cbatch ? (k < W1) : (k < W0);
            if (act){
                cc = sigf(fv)*cc + sigf(iv)*tanhf(gv);
                hh = sigf(ov)*tanhf(cc);
                int bb = cbatch ? b1 : b0;
                int eg = 64*(int)r + eloc;
                g_Hwb[((size_t)(bb*TLEN + k))*RNNH + eg] = __float2bfloat16(hh);
                g_Cw [((size_t)(bb*TLEN + k))*RNNH + eg] = cc;
            }
            float other = __shfl_xor_sync(0xffffffffu, hh, 1);
            if (!(eloc & 1)){
                __nv_bfloat162 pk = __floats2bfloat162_rn(hh, other);
                unsigned val = *(unsigned*)&pk;
                unsigned woff = (unsigned)(CH_HB + p2*1024 + cbatch*512
                                           + (32*(int)r + (eloc>>1))*4);
                unsigned moff = (unsigned)(CH_MB + p2*8);
                #pragma unroll
                for (int q = 0; q < 4; q++)
                    asm volatile("st.async.shared::cluster.mbarrier::complete_tx::bytes.b32 "
                                 "[%0], %1, [%2];"
                                 :: "r"(peer[q] + woff), "r"(val), "r"(peer[q] + moff)
                                 : "memory");
            }
        }
    }
    asm volatile("barrier.cluster.arrive.aligned;" ::: "memory");
    asm volatile("barrier.cluster.wait.aligned;"   ::: "memory");
}

// ---------------- K5: parallel per-step LSTM cell apply --------------------------
__global__ void k_apply(){
    int m = blockIdx.x;
    int d = threadIdx.x;          // 256
    int b = m >> 9;
    int j = g_cidx[m];
    size_t gbase = (size_t)m*GATES;
    float iv = __bfloat162float(g_G1b[gbase +       d]);
    float fv = __bfloat162float(g_G1b[gbase + 256 + d]);
    float gv = __bfloat162float(g_G1b[gbase + 512 + d]);
    float ov = __bfloat162float(g_G1b[gbase + 768 + d]);
    float cprev = 0.f;
    if (j >= 0){
        size_t hbase = (size_t)(b*TLEN + j)*GATES;
        iv += __bfloat162float(g_H2b[hbase +       d]);
        fv += __bfloat162float(g_H2b[hbase + 256 + d]);
        gv += __bfloat162float(g_H2b[hbase + 512 + d]);
        ov += __bfloat162float(g_H2b[hbase + 768 + d]);
        cprev = g_Cw[(size_t)(b*TLEN + j)*RNNH + d];
    }
    float cc = sigf(fv)*cprev + sigf(iv)*tanhf(gv);
    g_hsb[(size_t)m*RNNH + d] = __float2bfloat16(sigf(ov)*tanhf(cc));
}

// ---------------- K6: logits mma GEMM ([hs|enc] @ lw^T) + fused log_softmax ------
#define LG_SMEM (128*132*4)
__global__ void __launch_bounds__(256) k_logits(const int* __restrict__ lengths,
                                                float* __restrict__ out, int dup){
    __shared__ bf16 sA[128*SSTR];
    __shared__ bf16 sW[128*SSTR];
    float* sC = (float*)chsm;    // [128][132]
    int row0 = blockIdx.x * 128;
    int tid = threadIdx.x;
    int lane = tid & 31, wid = tid >> 5;
    int warp_m = wid & 3, warp_n = wid >> 2;
    int lrow = tid >> 2, lseg = tid & 3;

    unsigned sAb = (unsigned)__cvta_generic_to_shared(sA);
    unsigned sWb = (unsigned)__cvta_generic_to_shared(sW);
    unsigned aAddr = sAb + (unsigned)(((warp_m*32 + (lane&15))*SSTR + (lane>>4)*8)*2);
    unsigned bAddr = sWb + (unsigned)(((warp_n*64 + ((lane>>4)<<3) + (lane&7))*SSTR
                                      + ((lane>>3)&1)*8)*2);
    float acc[2][8][4];
    #pragma unroll
    for (int mi=0;mi<2;mi++)
        #pragma unroll
        for (int j=0;j<8;j++)
            #pragma unroll
            for (int q=0;q<4;q++) acc[mi][j][q] = 0.f;

    for (int k0 = 0; k0 < 768; k0 += 32){
        int kk = k0 + lseg*8;
        int m0 = row0 + lrow;
        uint4 a0, a1;
        if (kk < 256){
            a0 = *(const uint4*)&g_hsb[(size_t)m0*RNNH + kk];
            a1 = *(const uint4*)&g_hsb[(size_t)(m0+64)*RNNH + kk];
        } else {
            a0 = *(const uint4*)&g_encb[(size_t)m0*ENCD + kk - 256];
            a1 = *(const uint4*)&g_encb[(size_t)(m0+64)*ENCD + kk - 256];
        }
        uint4 w0 = *(const uint4*)&g_lwb[(size_t)lrow*768 + kk];
        uint4 w1 = *(const uint4*)&g_lwb[(size_t)(lrow+64)*768 + kk];
        *(uint4*)&sA[lrow*SSTR + lseg*8]      = a0;
        *(uint4*)&sA[(lrow+64)*SSTR + lseg*8] = a1;
        *(uint4*)&sW[lrow*SSTR + lseg*8]      = w0;
        *(uint4*)&sW[(lrow+64)*SSTR + lseg*8] = w1;
        __syncthreads();
        #pragma unroll
        for (int ks = 0; ks < 32; ks += 16){
            unsigned af[2][4], bfg[4][4];
            #pragma unroll
            for (int mi=0;mi<2;mi++)
                ldm_x4(aAddr + mi*16*SSTR*2 + ks*2, af[mi][0],af[mi][1],af[mi][2],af[mi][3]);
            #pragma unroll
            for (int p=0;p<4;p++)
                ldm_x4(bAddr + p*16*SSTR*2 + ks*2, bfg[p][0],bfg[p][1],bfg[p][2],bfg[p][3]);
            #pragma unroll
            for (int mi=0;mi<2;mi++)
                #pragma unroll
                for (int j=0;j<8;j++)
                    mma16816(acc[mi][j], af[mi], &bfg[j>>1][(j&1)*2]);
        }
        __syncthreads();
    }
    #pragma unroll
    for (int mi=0;mi<2;mi++)
        #pragma unroll
        for (int j=0;j<8;j++)
            #pragma unroll
            for (int q=0;q<2;q++){
                int rl = warp_m*32 + mi*16 + q*8 + (lane>>2);
                int cl = warp_n*64 + j*8 + (lane&3)*2;
                *(float2*)&sC[rl*132 + cl] = make_float2(acc[mi][j][q*2], acc[mi][j][q*2+1]);
            }
    __syncthreads();
    for (int rr = 0; rr < 16; rr++){
        int rl = wid*16 + rr;
        int m = row0 + rl;
        int b = m >> 9, t = m & 511;
        int L = lengths[b];
        float v[4];
        float vmax = -3.0e38f;
        #pragma unroll
        for (int u=0;u<4;u++){
            int n = lane + u*32;
            float x = sC[rl*132 + n];
            if (t == 0 && n == 0) x = -1e30f;
            if (t >= L) x = 0.f;
            v[u] = x;
            vmax = fmaxf(vmax, x);
        }
        #pragma unroll
        for (int d=16; d>=1; d>>=1) vmax = fmaxf(vmax, __shfl_xor_sync(0xffffffffu, vmax, d, 32));
        float ssum = 0.f;
        #pragma unroll
        for (int u=0;u<4;u++) ssum += expf(v[u] - vmax);
        #pragma unroll
        for (int d=16; d>=1; d>>=1) ssum += __shfl_xor_sync(0xffffffffu, ssum, d, 32);
        float lse = vmax + logf(ssum);
        #pragma unroll
        for (int u=0;u<4;u++){
            int n = lane + u*32;
            size_t idx = (size_t)m*LABEL + n;
            float res = v[u] - lse;
            out[idx] = res;
            if (dup) out[(size_t)OUTN + idx] = res;
        }
    }
}

// ---------------- launcher -------------------------------------------------------
extern "C" void kernel_launch(void* const* d_in, const int* in_sizes, int n_in,
                              void* d_out, int out_size){
    const float* enc  = (const float*)d_in[0];
    const int*   bnd  = (const int*)  d_in[1];
    const int*   pos  = (const int*)  d_in[2];
    const int*   len  = (const int*)  d_in[3];
    const float* w_ih = (const float*)d_in[4];
    const float* w_hh = (const float*)d_in[5];
    const float* b_ih = (const float*)d_in[6];
    const float* b_hh = (const float*)d_in[7];
    const float* ptab = (const float*)d_in[8];
    const float* lw   = (const float*)d_in[9];
    const float* cw   = (const float*)d_in[10];
    const float* cb   = (const float*)d_in[11];
    float* out = (float*)d_out;
    int dup = (out_size >= 2*OUTN) ? 1 : 0;

    void* p;
    cudaGetSymbolAddress(&p, g_zinb);   bf16* zinb = (bf16*)p;
    cudaGetSymbolAddress(&p, g_zb);     bf16* zb   = (bf16*)p;
    cudaGetSymbolAddress(&p, g_G1b);    bf16* G1b  = (bf16*)p;
    cudaGetSymbolAddress(&p, g_Hwb);    bf16* Hwb  = (bf16*)p;
    cudaGetSymbolAddress(&p, g_H2b);    bf16* H2b  = (bf16*)p;
    cudaGetSymbolAddress(&p, g_cwb);    bf16* cwb  = (bf16*)p;
    cudaGetSymbolAddress(&p, g_wihb);   bf16* wihb = (bf16*)p;
    cudaGetSymbolAddress(&p, g_whh_bf); bf16* whhb = (bf16*)p;

    static int attr_done = 0;
    if (!attr_done){
        cudaFuncSetAttribute(k_chain,  cudaFuncAttributeMaxDynamicSharedMemorySize, CH_SMEM);
        cudaFuncSetAttribute(k_logits, cudaFuncAttributeMaxDynamicSharedMemorySize, LG_SMEM);
        attr_done = 1;
    }

    // launch 0: all conversions fused
    k_convert_all<<<(N_ALL4 + 255)/256, 256>>>(enc, cw, w_ih, w_hh, lw);
    // launch 1: ballot scan metadata
    k_scan_meta<<<2, 1024>>>(bnd);
    // launch 2: zin build
    k_build_zin<<<dim3(5, BATCH), 128>>>(enc, bnd, pos, ptab);
    // launch 3: z = tanh(zin @ combine_w^T + combine_b), t==0 rows zeroed
    k_gemm_mma<0><<<dim3(RNNH/128, MROWS/128), 256>>>(zinb, cwb, zb, ZK, RNNH, cb, cb);
    // launch 4: G1 = z @ w_ih^T + b_ih + b_hh
    k_gemm_mma<1><<<dim3(GATES/128, MROWS/128), 256>>>(zb, wihb, G1b, RNNH, GATES, b_ih, b_hh);
    // launch 5 (ncu -s 5 lands here): carry chain
    k_chain<<<(BATCH/2)*4, 256, CH_SMEM>>>();
    // launch 6: H2 = Hw @ w_hh^T (ragged skip)
    k_gemm_mma<2><<<dim3(GATES/128, MROWS/128), 256>>>(Hwb, whhb, H2b, RNNH, GATES, nullptr, nullptr);
    // launch 7: parallel per-step LSTM outputs
    k_apply<<<MROWS, 256>>>();
    // launch 8: logits + masking + log_softmax
    k_logits<<<MROWS/128, 256, LG_SMEM>>>(len, out, dup);
}

// round 10
// speedup vs baseline: 6.9452x; 1.1385x over previous
#include <cuda_runtime.h>
#include <cuda_bf16.h>
#include <cstdint>
#include <math.h>

#define BATCH 64
#define TLEN  512
#define RNNH  256
#define ENCD  512
#define ZK    640
#define GATES 1024
#define LABEL 128
#define MROWS (BATCH*TLEN)          /* 32768 */
#define OUTN  (4194304)             /* MROWS*LABEL */

typedef __nv_bfloat16 bf16;

// ---------------- scratch (device globals; no allocation allowed) ----------------
__device__ __align__(16) bf16  g_zinb[(size_t)MROWS*ZK];    // [B*T,640] pe|pool (bf16)
__device__ __align__(16) bf16  g_G1b[(size_t)MROWS*GATES];  // z@w_ih^T + b_ih + b_hh (bf16)
__device__ __align__(16) bf16  g_Hwb[(size_t)MROWS*RNNH];   // per-word carry h_j (bf16)
__device__ __align__(16) float g_Cw [(size_t)MROWS*RNNH];   // per-word carry c_j (fp32)
__device__ __align__(16) bf16  g_H2b[(size_t)MROWS*GATES];  // Hw@w_hh^T (bf16)
__device__ __align__(16) bf16  g_hsb[(size_t)MROWS*RNNH];   // per-step LSTM output (bf16)
__device__ __align__(16) bf16  g_encb[(size_t)MROWS*ENCD];  // encoder_out bf16
__device__ __align__(16) bf16  g_cwb [RNNH*ZK];
__device__ __align__(16) bf16  g_wihb[GATES*RNNH];
__device__ __align__(16) bf16  g_whh_bf[GATES*RNNH];
__device__ __align__(16) bf16  g_lwb [LABEL*768];
__device__ int   g_svec[MROWS];
__device__ int   g_cidx[MROWS];
__device__ int   g_bpos[MROWS];
__device__ int   g_wcnt[BATCH];

__device__ __forceinline__ float sigf(float x){ return 1.f/(1.f+expf(-x)); }

// ---------------- L0: all f32->bf16 conversions + ballot boundary scan -----------
#define N_ENC4 (MROWS*ENCD/4)
#define N_CW4  (RNNH*ZK/4)
#define N_W4   (GATES*RNNH/4)
#define N_LW4  (LABEL*768/4)
#define N_ALL4 (N_ENC4 + N_CW4 + N_W4 + N_W4 + N_LW4)
#define CONV_BLOCKS ((N_ALL4 + 255)/256)

__device__ __forceinline__ void cvt4(const float* s, bf16* d, long i){
    float4 v = *(const float4*)(s + i*4);
    __nv_bfloat162* o = (__nv_bfloat162*)(d + i*4);
    o[0] = __floats2bfloat162_rn(v.x, v.y);
    o[1] = __floats2bfloat162_rn(v.z, v.w);
}
__global__ void k_conv_scan(const float* __restrict__ enc, const float* __restrict__ cw,
                            const float* __restrict__ wih, const float* __restrict__ whh,
                            const float* __restrict__ lw, const int* __restrict__ bnd){
    if (blockIdx.x < CONV_BLOCKS){
        long i = (long)blockIdx.x*256 + threadIdx.x;
        if (i < N_ENC4){ cvt4(enc, g_encb, i); return; }
        i -= N_ENC4;
        if (i < N_CW4){ cvt4(cw, g_cwb, i); return; }
        i -= N_CW4;
        if (i < N_W4){ cvt4(wih, g_wihb, i); return; }
        i -= N_W4;
        if (i < N_W4){ cvt4(whh, g_whh_bf, i); return; }
        i -= N_W4;
        if (i < N_LW4){ cvt4(lw, g_lwb, i); }
    } else {
        int warp = (blockIdx.x - CONV_BLOCKS)*8 + (threadIdx.x >> 5);  // 0..63
        int lane = threadIdx.x & 31;
        if (warp >= BATCH) return;
        int base = warp*TLEN;
        int cnt = 0, last = 0;
        for (int c = 0; c < TLEN/32; c++){
            int t = c*32 + lane;
            int bv = bnd[base + t];
            unsigned m = __ballot_sync(0xffffffffu, bv == 1);
            unsigned mlt = m & ((1u << lane) - 1u);
            int sv = mlt ? (c*32 + 31 - __clz(mlt)) : last;
            g_svec[base + t] = sv;
            g_cidx[base + t] = cnt + __popc(mlt) - 1;
            if (bv == 1) g_bpos[base + cnt + __popc(mlt)] = t;
            cnt += __popc(m);
            last = m ? (c*32 + 31 - __clz(m)) : last;
        }
        if (lane == 0) g_wcnt[warp] = cnt;
    }
}

// ---------------- L1: build zin = [pos_emb(128) | running word mean(512)] --------
// grid (2, B), 512 threads. x=0: pe (fully parallel over t). x=1: pool (serial t,
// all 512 dims in one block, 4x unrolled with register prefetch).
__global__ void __launch_bounds__(512) k_build_zin(
        const float* __restrict__ enc, const int* __restrict__ bnd,
        const int* __restrict__ pos, const float* __restrict__ ptab){
    int b = blockIdx.y;
    int tid = threadIdx.x;
    if (blockIdx.x == 0){
        int dim = tid & 127, tq = tid >> 7;
        for (int t = tq; t < TLEN; t += 4){
            int s = g_svec[b*TLEN + t];
            int p = pos[b*TLEN + s];
            g_zinb[(size_t)(b*TLEN + t)*ZK + dim] = __float2bfloat16(ptab[p*128 + dim]);
        }
    } else {
        int dim = tid;  // 0..511
        float acc = 0.f;
        for (int t = 0; t < TLEN; t += 4){
            float e[4]; int s[4], bb[4];
            #pragma unroll
            for (int j = 0; j < 4; j++){
                e[j]  = enc[(size_t)(b*TLEN + t + j)*ENCD + dim];
                s[j]  = g_svec[b*TLEN + t + j];
                bb[j] = bnd[b*TLEN + t + j];
            }
            #pragma unroll
            for (int j = 0; j < 4; j++){
                int wl = (t + j) - s[j]; if (wl < 1) wl = 1;
                g_zinb[(size_t)(b*TLEN + t + j)*ZK + 128 + dim] =
                    __float2bfloat16(acc / (float)wl);
                acc = (bb[j] == 1) ? e[j] : (acc + e[j]);
            }
        }
    }
}

// ================= mma primitives =================================================
#define SSTR 40  /* smem row stride in bf16 elems (80B, conflict-free for ldmatrix) */

__device__ __forceinline__ void ldm_x4(unsigned addr, unsigned& r0, unsigned& r1,
                                       unsigned& r2, unsigned& r3){
    asm volatile("ldmatrix.sync.aligned.m8n8.x4.shared.b16 {%0,%1,%2,%3}, [%4];"
                 : "=r"(r0), "=r"(r1), "=r"(r2), "=r"(r3) : "r"(addr));
}
__device__ __forceinline__ void mma16816(float* c, const unsigned* a, const unsigned* b){
    asm volatile("mma.sync.aligned.m16n8k16.row.col.f32.bf16.bf16.f32 "
                 "{%0,%1,%2,%3}, {%4,%5,%6,%7}, {%8,%9}, {%0,%1,%2,%3};"
                 : "+f"(c[0]), "+f"(c[1]), "+f"(c[2]), "+f"(c[3])
                 : "r"(a[0]), "r"(a[1]), "r"(a[2]), "r"(a[3]), "r"(b[0]), "r"(b[1]));
}

// ---------------- L2: fused z + G1 GEMM ------------------------------------------
// Per block: rows [row0,row0+128). Stage 1: z = tanh(zin@cw^T+cb) ([128x256],
// K=640), written into smem zS in 8 ldmatrix-layout k-tiles [128][SSTR].
// Stage 2: G1 = z@wih^T + b_ih + b_hh ([128x1024], K=256), A from zS, B from gmem.
#define ZS_OFF   0
#define ZS_TILE  (128*SSTR*2)          /* 10240 B per k-tile */
#define ZG_SA    (8*ZS_TILE)           /* 81920 */
#define ZG_SW    (ZG_SA + 128*SSTR*2)  /* 92160 */
#define ZG_SMEM  (ZG_SW + 128*SSTR*2)  /* 102400 */
extern __shared__ char chsm[];

__global__ void __launch_bounds__(256) k_zg1(const float* __restrict__ cb,
                                             const float* __restrict__ bih,
                                             const float* __restrict__ bhh){
    bf16* zS = (bf16*)(chsm + ZS_OFF);
    bf16* sA = (bf16*)(chsm + ZG_SA);
    bf16* sW = (bf16*)(chsm + ZG_SW);
    int row0 = blockIdx.x * 128;
    int tid = threadIdx.x;
    int lane = tid & 31, wid = tid >> 5;
    int warp_m = wid & 3, warp_n = wid >> 2;
    int lrow = tid >> 2, lseg = tid & 3;

    unsigned sAb = (unsigned)__cvta_generic_to_shared(sA);
    unsigned sWb = (unsigned)__cvta_generic_to_shared(sW);
    unsigned zSb = (unsigned)__cvta_generic_to_shared(zS);
    unsigned aOff = (unsigned)(((warp_m*32 + (lane&15))*SSTR + (lane>>4)*8)*2);
    unsigned bOff = (unsigned)(((warp_n*64 + ((lane>>4)<<3) + (lane&7))*SSTR
                               + ((lane>>3)&1)*8)*2);

    // ---------------- stage 1: z tile (two 128-col halves) ----------------
    for (int ch = 0; ch < 2; ch++){
        int col0 = ch*128;
        const bf16* Ap = g_zinb + (size_t)(row0 + lrow)*ZK + lseg*8;
        const bf16* Wp = g_cwb  + (size_t)(col0 + lrow)*ZK + lseg*8;
        float acc[2][8][4];
        #pragma unroll
        for (int mi=0;mi<2;mi++)
            #pragma unroll
            for (int j=0;j<8;j++)
                #pragma unroll
                for (int q=0;q<4;q++) acc[mi][j][q] = 0.f;
        uint4 a0 = *(const uint4*)(Ap);
        uint4 a1 = *(const uint4*)(Ap + (size_t)64*ZK);
        uint4 w0 = *(const uint4*)(Wp);
        uint4 w1 = *(const uint4*)(Wp + (size_t)64*ZK);
        for (int k0 = 0; k0 < ZK; k0 += 32){
            *(uint4*)&sA[lrow*SSTR + lseg*8]       = a0;
            *(uint4*)&sA[(lrow+64)*SSTR + lseg*8]  = a1;
            *(uint4*)&sW[lrow*SSTR + lseg*8]       = w0;
            *(uint4*)&sW[(lrow+64)*SSTR + lseg*8]  = w1;
            __syncthreads();
            if (k0 + 32 < ZK){
                a0 = *(const uint4*)(Ap + k0 + 32);
                a1 = *(const uint4*)(Ap + (size_t)64*ZK + k0 + 32);
                w0 = *(const uint4*)(Wp + k0 + 32);
                w1 = *(const uint4*)(Wp + (size_t)64*ZK + k0 + 32);
            }
            #pragma unroll
            for (int ks = 0; ks < 32; ks += 16){
                unsigned af[2][4], bfg[4][4];
                #pragma unroll
                for (int mi=0;mi<2;mi++)
                    ldm_x4(sAb + aOff + mi*16*SSTR*2 + ks*2,
                           af[mi][0],af[mi][1],af[mi][2],af[mi][3]);
                #pragma unroll
                for (int p=0;p<4;p++)
                    ldm_x4(sWb + bOff + p*16*SSTR*2 + ks*2,
                           bfg[p][0],bfg[p][1],bfg[p][2],bfg[p][3]);
                #pragma unroll
                for (int mi=0;mi<2;mi++)
                    #pragma unroll
                    for (int j=0;j<8;j++)
                        mma16816(acc[mi][j], af[mi], &bfg[j>>1][(j&1)*2]);
            }
            __syncthreads();
        }
        // epilogue -> zS k-tiles (tanh + bias + zero first row of each batch)
        #pragma unroll
        for (int mi=0;mi<2;mi++){
            #pragma unroll
            for (int j=0;j<8;j++){
                #pragma unroll
                for (int q=0;q<2;q++){
                    int ml = warp_m*32 + mi*16 + q*8 + (lane>>2);
                    int n  = col0 + warp_n*64 + j*8 + (lane&3)*2;
                    float v0 = tanhf(acc[mi][j][q*2+0] + cb[n]);
                    float v1 = tanhf(acc[mi][j][q*2+1] + cb[n+1]);
                    if (((row0 + ml) & 511) == 0){ v0 = 0.f; v1 = 0.f; }
                    int kt = n >> 5, kk = n & 31;
                    *(__nv_bfloat162*)&zS[kt*128*SSTR + ml*SSTR + kk] =
                        __floats2bfloat162_rn(v0, v1);
                }
            }
        }
        __syncthreads();
    }

    // ---------------- stage 2: G1 = z @ wih^T, 8 n-tiles ----------------
    for (int nt = 0; nt < 8; nt++){
        int col0 = nt*128;
        const bf16* Wp = g_wihb + (size_t)(col0 + lrow)*RNNH + lseg*8;
        float acc[2][8][4];
        #pragma unroll
        for (int mi=0;mi<2;mi++)
            #pragma unroll
            for (int j=0;j<8;j++)
                #pragma unroll
                for (int q=0;q<4;q++) acc[mi][j][q] = 0.f;
        uint4 w0 = *(const uint4*)(Wp);
        uint4 w1 = *(const uint4*)(Wp + (size_t)64*RNNH);
        for (int kt = 0; kt < 8; kt++){
            *(uint4*)&sW[lrow*SSTR + lseg*8]       = w0;
            *(uint4*)&sW[(lrow+64)*SSTR + lseg*8]  = w1;
            __syncthreads();
            if (kt < 7){
                w0 = *(const uint4*)(Wp + (kt+1)*32);
                w1 = *(const uint4*)(Wp + (size_t)64*RNNH + (kt+1)*32);
            }
            unsigned zBase = zSb + kt*ZS_TILE;
            #pragma unroll
            for (int ks = 0; ks < 32; ks += 16){
                unsigned af[2][4], bfg[4][4];
                #pragma unroll
                for (int mi=0;mi<2;mi++)
                    ldm_x4(zBase + aOff + mi*16*SSTR*2 + ks*2,
                           af[mi][0],af[mi][1],af[mi][2],af[mi][3]);
                #pragma unroll
                for (int p=0;p<4;p++)
                    ldm_x4(sWb + bOff + p*16*SSTR*2 + ks*2,
                           bfg[p][0],bfg[p][1],bfg[p][2],bfg[p][3]);
                #pragma unroll
                for (int mi=0;mi<2;mi++)
                    #pragma unroll
                    for (int j=0;j<8;j++)
                        mma16816(acc[mi][j], af[mi], &bfg[j>>1][(j&1)*2]);
            }
            __syncthreads();
        }
        #pragma unroll
        for (int mi=0;mi<2;mi++){
            #pragma unroll
            for (int j=0;j<8;j++){
                #pragma unroll
                for (int q=0;q<2;q++){
                    int m = row0 + warp_m*32 + mi*16 + q*8 + (lane>>2);
                    int n = col0 + warp_n*64 + j*8 + (lane&3)*2;
                    float v0 = acc[mi][j][q*2+0] + bih[n]   + bhh[n];
                    float v1 = acc[mi][j][q*2+1] + bih[n+1] + bhh[n+1];
                    *(__nv_bfloat162*)&g_G1b[(size_t)m*GATES + n] =
                        __floats2bfloat162_rn(v0, v1);
                }
            }
        }
    }
}

// ---------------- generic bf16 mma GEMM (used for H2, EPI 2 only) -----------------
template<int EPI>
__global__ void __launch_bounds__(256) k_gemm_mma(
        const bf16* __restrict__ A, const bf16* __restrict__ W,
        bf16* __restrict__ Cb, int K, int N,
        const float* __restrict__ bias1, const float* __restrict__ bias2){
    int row0 = blockIdx.y * 128;
    int col0 = blockIdx.x * 128;
    if (EPI == 2){
        int b = row0 >> 9;
        if ((row0 & 511) >= g_wcnt[b]) return;
    }
    __shared__ bf16 sA[128*SSTR];
    __shared__ bf16 sW[128*SSTR];
    int tid = threadIdx.x;
    int lane = tid & 31, wid = tid >> 5;
    int warp_m = wid & 3, warp_n = wid >> 2;
    int lrow = tid >> 2, lseg = tid & 3;

    const bf16* Ap = A + (size_t)(row0 + lrow)*K + lseg*8;
    const bf16* Wp = W + (size_t)(col0 + lrow)*K + lseg*8;

    unsigned sAb = (unsigned)__cvta_generic_to_shared(sA);
    unsigned sWb = (unsigned)__cvta_generic_to_shared(sW);
    unsigned aAddr = sAb + (unsigned)(((warp_m*32 + (lane&15))*SSTR + (lane>>4)*8)*2);
    unsigned bAddr = sWb + (unsigned)(((warp_n*64 + ((lane>>4)<<3) + (lane&7))*SSTR
                                      + ((lane>>3)&1)*8)*2);
    float acc[2][8][4];
    #pragma unroll
    for (int mi=0;mi<2;mi++)
        #pragma unroll
        for (int j=0;j<8;j++)
            #pragma unroll
            for (int q=0;q<4;q++) acc[mi][j][q] = 0.f;

    uint4 a0 = *(const uint4*)(Ap);
    uint4 a1 = *(const uint4*)(Ap + (size_t)64*K);
    uint4 w0 = *(const uint4*)(Wp);
    uint4 w1 = *(const uint4*)(Wp + (size_t)64*K);

    for (int k0 = 0; k0 < K; k0 += 32){
        *(uint4*)&sA[lrow*SSTR + lseg*8]       = a0;
        *(uint4*)&sA[(lrow+64)*SSTR + lseg*8]  = a1;
        *(uint4*)&sW[lrow*SSTR + lseg*8]       = w0;
        *(uint4*)&sW[(lrow+64)*SSTR + lseg*8]  = w1;
        __syncthreads();
        if (k0 + 32 < K){
            a0 = *(const uint4*)(Ap + k0 + 32);
            a1 = *(const uint4*)(Ap + (size_t)64*K + k0 + 32);
            w0 = *(const uint4*)(Wp + k0 + 32);
            w1 = *(const uint4*)(Wp + (size_t)64*K + k0 + 32);
        }
        #pragma unroll
        for (int ks = 0; ks < 32; ks += 16){
            unsigned af[2][4], bfg[4][4];
            #pragma unroll
            for (int mi=0;mi<2;mi++)
                ldm_x4(aAddr + mi*16*SSTR*2 + ks*2, af[mi][0],af[mi][1],af[mi][2],af[mi][3]);
            #pragma unroll
            for (int p=0;p<4;p++)
                ldm_x4(bAddr + p*16*SSTR*2 + ks*2, bfg[p][0],bfg[p][1],bfg[p][2],bfg[p][3]);
            #pragma unroll
            for (int mi=0;mi<2;mi++)
                #pragma unroll
                for (int j=0;j<8;j++)
                    mma16816(acc[mi][j], af[mi], &bfg[j>>1][(j&1)*2]);
        }
        __syncthreads();
    }
    #pragma unroll
    for (int mi=0;mi<2;mi++){
        #pragma unroll
        for (int j=0;j<8;j++){
            #pragma unroll
            for (int q=0;q<2;q++){
                int m = row0 + warp_m*32 + mi*16 + q*8 + (lane>>2);
                int n = col0 + warp_n*64 + j*8 + (lane&3)*2;
                *(__nv_bfloat162*)&Cb[(size_t)m*N + n] =
                    __floats2bfloat162_rn(acc[mi][j][q*2+0], acc[mi][j][q*2+1]);
            }
        }
    }
}

// ---------------- L3: cluster-4 chain, h-partitioned, st.async exchange ----------
#define CH_SW   0
#define CH_HB   131072                 /* [2 parity][2 batch][512B] = 2048 */
#define CH_SG   (CH_HB + 2048)         /* [2 parity][2 batch][256] fp32 = 4096 */
#define CH_MB   (CH_SG + 4096)         /* 2 mbarriers */
#define CH_SMEM (CH_MB + 64)
#define CH_TXB  1024                   /* bytes per mbar phase */

__device__ __forceinline__ void mbar_wait_cluster(unsigned addr, unsigned parity){
    unsigned done = 0;
    while (!done){
        asm volatile(
            "{\n\t.reg .pred p;\n\t"
            "mbarrier.try_wait.parity.acquire.cluster.shared::cta.b64 p, [%1], %2, 0x989680;\n\t"
            "selp.b32 %0, 1, 0, p;\n\t}"
            : "=r"(done) : "r"(addr), "r"(parity) : "memory");
    }
}

__global__ void __cluster_dims__(4,1,1) __launch_bounds__(256, 1) k_chain(){
    uint4* sw4  = (uint4*)(chsm + CH_SW);            // [32 cb][256 rows]
    uint4* hb4  = (uint4*)(chsm + CH_HB);            // [2p][2b][32 cb]
    float* sg   = (float*)(chsm + CH_SG);            // [2p][2b][256]
    unsigned mb = (unsigned)__cvta_generic_to_shared(chsm + CH_MB);
    unsigned smem_base = (unsigned)__cvta_generic_to_shared(chsm);
    int tid = threadIdx.x;                           // 256
    unsigned r; asm("mov.u32 %0, %%cluster_ctarank;" : "=r"(r));
    int c = blockIdx.x >> 2;
    int b0 = 2*c, b1 = 2*c + 1;

    for (int idx = tid; idx < 256*32; idx += 256){
        int l = idx >> 5, cb2 = idx & 31;
        int G = (l >> 6)*256 + 64*(int)r + (l & 63);
        sw4[cb2*256 + l] = ((const uint4*)&g_whh_bf[(size_t)G*256])[cb2];
    }
    if (tid < 128) hb4[tid] = make_uint4(0,0,0,0);
    if (tid == 0){
        asm volatile("mbarrier.init.shared.b64 [%0], %1;" :: "r"(mb),   "r"(1) : "memory");
        asm volatile("mbarrier.init.shared.b64 [%0], %1;" :: "r"(mb+8), "r"(1) : "memory");
        asm volatile("mbarrier.arrive.expect_tx.shared::cta.b64 _, [%0], %1;"
                     :: "r"(mb),   "r"(CH_TXB) : "memory");
        asm volatile("mbarrier.arrive.expect_tx.shared::cta.b64 _, [%0], %1;"
                     :: "r"(mb+8), "r"(CH_TXB) : "memory");
    }
    __syncthreads();
    asm volatile("barrier.cluster.arrive.aligned;" ::: "memory");
    asm volatile("barrier.cluster.wait.aligned;"   ::: "memory");

    int W0 = g_wcnt[b0], W1 = g_wcnt[b1];
    int Wmax = (W0 > W1) ? W0 : W1;

    unsigned peer[4];
    #pragma unroll
    for (int q = 0; q < 4; q++)
        asm("mapa.shared::cluster.u32 %0, %1, %2;" : "=r"(peer[q]) : "r"(smem_base), "r"(q));

    int grow = (tid >> 6)*256 + 64*(int)r + (tid & 63);
    const bf16* g1p0 = &g_G1b[((size_t)b0*TLEN)*GATES + grow];
    const bf16* g1p1 = &g_G1b[((size_t)b1*TLEN)*GATES + grow];
    int cbatch = tid >> 6;
    int eloc   = tid & 63;
    float cc = 0.f, hh = 0.f;
    int ph[2] = {0, 0};

    for (int k = 0; k < Wmax; k++){
        int p = k & 1, p2 = p ^ 1;
        if (k > 0){
            mbar_wait_cluster(mb + p*8, (unsigned)ph[p]);
            ph[p] ^= 1;
            if (tid == 0)
                asm volatile("mbarrier.arrive.expect_tx.shared::cta.b64 _, [%0], %1;"
                             :: "r"(mb + p*8), "r"(CH_TXB) : "memory");
        }
        int t0 = (k < W0) ? g_bpos[b0*TLEN + k] : 0;
        int t1 = (k < W1) ? g_bpos[b1*TLEN + k] : 0;
        float g10 = __bfloat162float(g1p0[(size_t)t0*GATES]);
        float g11 = __bfloat162float(g1p1[(size_t)t1*GATES]);
        __nv_bfloat162 zz = __floats2bfloat162_rn(0.f, 0.f);
        __nv_bfloat162 a0a = zz, a0b = zz, a1a = zz, a1b = zz;
        const uint4* h0p = &hb4[p*64];
        const uint4* h1p = &hb4[p*64 + 32];
        #pragma unroll 8
        for (int cb2 = 0; cb2 < 32; cb2++){
            uint4 w  = sw4[cb2*256 + tid];
            uint4 h0 = h0p[cb2];
            uint4 h1 = h1p[cb2];
            const __nv_bfloat162* wp  = (const __nv_bfloat162*)&w;
            const __nv_bfloat162* hp0 = (const __nv_bfloat162*)&h0;
            const __nv_bfloat162* hp1 = (const __nv_bfloat162*)&h1;
            a0a = __hfma2(wp[0], hp0[0], a0a); a0b = __hfma2(wp[1], hp0[1], a0b);
            a0a = __hfma2(wp[2], hp0[2], a0a); a0b = __hfma2(wp[3], hp0[3], a0b);
            a1a = __hfma2(wp[0], hp1[0], a1a); a1b = __hfma2(wp[1], hp1[1], a1b);
            a1a = __hfma2(wp[2], hp1[2], a1a); a1b = __hfma2(wp[3], hp1[3], a1b);
        }
        float2 f0a = __bfloat1622float2(a0a), f0b = __bfloat1622float2(a0b);
        float2 f1a = __bfloat1622float2(a1a), f1b = __bfloat1622float2(a1b);
        sg[p*512 +       tid] = g10 + (f0a.x + f0a.y) + (f0b.x + f0b.y);
        sg[p*512 + 256 + tid] = g11 + (f1a.x + f1a.y) + (f1b.x + f1b.y);
        __syncthreads();
        if (tid < 128){
            const float* s = &sg[p*512 + cbatch*256];
            float iv = s[eloc], fv = s[64+eloc], gv = s[128+eloc], ov = s[192+eloc];
            bool act = cbatch ? (k < W1) : (k < W0);
            if (act){
                cc = sigf(fv)*cc + sigf(iv)*tanhf(gv);
                hh = sigf(ov)*tanhf(cc);
                int bb = cbatch ? b1 : b0;
                int eg = 64*(int)r + eloc;
                g_Hwb[((size_t)(bb*TLEN + k))*RNNH + eg] = __float2bfloat16(hh);
                g_Cw [((size_t)(bb*TLEN + k))*RNNH + eg] = cc;
            }
            float other = __shfl_xor_sync(0xffffffffu, hh, 1);
            if (!(eloc & 1)){
                __nv_bfloat162 pk = __floats2bfloat162_rn(hh, other);
                unsigned val = *(unsigned*)&pk;
                unsigned woff = (unsigned)(CH_HB + p2*1024 + cbatch*512
                                           + (32*(int)r + (eloc>>1))*4);
                unsigned moff = (unsigned)(CH_MB + p2*8);
                #pragma unroll
                for (int q = 0; q < 4; q++)
                    asm volatile("st.async.shared::cluster.mbarrier::complete_tx::bytes.b32 "
                                 "[%0], %1, [%2];"
                                 :: "r"(peer[q] + woff), "r"(val), "r"(peer[q] + moff)
                                 : "memory");
            }
        }
    }
    asm volatile("barrier.cluster.arrive.aligned;" ::: "memory");
    asm volatile("barrier.cluster.wait.aligned;"   ::: "memory");
}

// ---------------- L5: parallel per-step LSTM cell apply --------------------------
__global__ void k_apply(){
    int m = blockIdx.x;
    int d = threadIdx.x;          // 256
    int b = m >> 9;
    int j = g_cidx[m];
    size_t gbase = (size_t)m*GATES;
    float iv = __bfloat162float(g_G1b[gbase +       d]);
    float fv = __bfloat162float(g_G1b[gbase + 256 + d]);
    float gv = __bfloat162float(g_G1b[gbase + 512 + d]);
    float ov = __bfloat162float(g_G1b[gbase + 768 + d]);
    float cprev = 0.f;
    if (j >= 0){
        size_t hbase = (size_t)(b*TLEN + j)*GATES;
        iv += __bfloat162float(g_H2b[hbase +       d]);
        fv += __bfloat162float(g_H2b[hbase + 256 + d]);
        gv += __bfloat162float(g_H2b[hbase + 512 + d]);
        ov += __bfloat162float(g_H2b[hbase + 768 + d]);
        cprev = g_Cw[(size_t)(b*TLEN + j)*RNNH + d];
    }
    float cc = sigf(fv)*cprev + sigf(iv)*tanhf(gv);
    g_hsb[(size_t)m*RNNH + d] = __float2bfloat16(sigf(ov)*tanhf(cc));
}

// ---------------- L6: logits mma GEMM ([hs|enc] @ lw^T) + fused log_softmax ------
#define LG_SMEM (128*132*4)
__global__ void __launch_bounds__(256) k_logits(const int* __restrict__ lengths,
                                                float* __restrict__ out, int dup){
    __shared__ bf16 sA[128*SSTR];
    __shared__ bf16 sW[128*SSTR];
    float* sC = (float*)chsm;    // [128][132]
    int row0 = blockIdx.x * 128;
    int tid = threadIdx.x;
    int lane = tid & 31, wid = tid >> 5;
    int warp_m = wid & 3, warp_n = wid >> 2;
    int lrow = tid >> 2, lseg = tid & 3;

    unsigned sAb = (unsigned)__cvta_generic_to_shared(sA);
    unsigned sWb = (unsigned)__cvta_generic_to_shared(sW);
    unsigned aAddr = sAb + (unsigned)(((warp_m*32 + (lane&15))*SSTR + (lane>>4)*8)*2);
    unsigned bAddr = sWb + (unsigned)(((warp_n*64 + ((lane>>4)<<3) + (lane&7))*SSTR
                                      + ((lane>>3)&1)*8)*2);
    float acc[2][8][4];
    #pragma unroll
    for (int mi=0;mi<2;mi++)
        #pragma unroll
        for (int j=0;j<8;j++)
            #pragma unroll
            for (int q=0;q<4;q++) acc[mi][j][q] = 0.f;

    for (int k0 = 0; k0 < 768; k0 += 32){
        int kk = k0 + lseg*8;
        int m0 = row0 + lrow;
        uint4 a0, a1;
        if (kk < 256){
            a0 = *(const uint4*)&g_hsb[(size_t)m0*RNNH + kk];
            a1 = *(const uint4*)&g_hsb[(size_t)(m0+64)*RNNH + kk];
        } else {
            a0 = *(const uint4*)&g_encb[(size_t)m0*ENCD + kk - 256];
            a1 = *(const uint4*)&g_encb[(size_t)(m0+64)*ENCD + kk - 256];
        }
        uint4 w0 = *(const uint4*)&g_lwb[(size_t)lrow*768 + kk];
        uint4 w1 = *(const uint4*)&g_lwb[(size_t)(lrow+64)*768 + kk];
        *(uint4*)&sA[lrow*SSTR + lseg*8]      = a0;
        *(uint4*)&sA[(lrow+64)*SSTR + lseg*8] = a1;
        *(uint4*)&sW[lrow*SSTR + lseg*8]      = w0;
        *(uint4*)&sW[(lrow+64)*SSTR + lseg*8] = w1;
        __syncthreads();
        #pragma unroll
        for (int ks = 0; ks < 32; ks += 16){
            unsigned af[2][4], bfg[4][4];
            #pragma unroll
            for (int mi=0;mi<2;mi++)
                ldm_x4(aAddr + mi*16*SSTR*2 + ks*2, af[mi][0],af[mi][1],af[mi][2],af[mi][3]);
            #pragma unroll
            for (int p=0;p<4;p++)
                ldm_x4(bAddr + p*16*SSTR*2 + ks*2, bfg[p][0],bfg[p][1],bfg[p][2],bfg[p][3]);
            #pragma unroll
            for (int mi=0;mi<2;mi++)
                #pragma unroll
                for (int j=0;j<8;j++)
                    mma16816(acc[mi][j], af[mi], &bfg[j>>1][(j&1)*2]);
        }
        __syncthreads();
    }
    #pragma unroll
    for (int mi=0;mi<2;mi++)
        #pragma unroll
        for (int j=0;j<8;j++)
            #pragma unroll
            for (int q=0;q<2;q++){
                int rl = warp_m*32 + mi*16 + q*8 + (lane>>2);
                int cl = warp_n*64 + j*8 + (lane&3)*2;
                *(float2*)&sC[rl*132 + cl] = make_float2(acc[mi][j][q*2], acc[mi][j][q*2+1]);
            }
    __syncthreads();
    for (int rr = 0; rr < 16; rr++){
        int rl = wid*16 + rr;
        int m = row0 + rl;
        int b = m >> 9, t = m & 511;
        int L = lengths[b];
        float v[4];
        float vmax = -3.0e38f;
        #pragma unroll
        for (int u=0;u<4;u++){
            int n = lane + u*32;
            float x = sC[rl*132 + n];
            if (t == 0 && n == 0) x = -1e30f;
            if (t >= L) x = 0.f;
            v[u] = x;
            vmax = fmaxf(vmax, x);
        }
        #pragma unroll
        for (int d=16; d>=1; d>>=1) vmax = fmaxf(vmax, __shfl_xor_sync(0xffffffffu, vmax, d, 32));
        float ssum = 0.f;
        #pragma unroll
        for (int u=0;u<4;u++) ssum += expf(v[u] - vmax);
        #pragma unroll
        for (int d=16; d>=1; d>>=1) ssum += __shfl_xor_sync(0xffffffffu, ssum, d, 32);
        float lse = vmax + logf(ssum);
        #pragma unroll
        for (int u=0;u<4;u++){
            int n = lane + u*32;
            size_t idx = (size_t)m*LABEL + n;
            float res = v[u] - lse;
            out[idx] = res;
            if (dup) out[(size_t)OUTN + idx] = res;
        }
    }
}

// ---------------- launcher -------------------------------------------------------
extern "C" void kernel_launch(void* const* d_in, const int* in_sizes, int n_in,
                              void* d_out, int out_size){
    const float* enc  = (const float*)d_in[0];
    const int*   bnd  = (const int*)  d_in[1];
    const int*   pos  = (const int*)  d_in[2];
    const int*   len  = (const int*)  d_in[3];
    const float* w_ih = (const float*)d_in[4];
    const float* w_hh = (const float*)d_in[5];
    const float* b_ih = (const float*)d_in[6];
    const float* b_hh = (const float*)d_in[7];
    const float* ptab = (const float*)d_in[8];
    const float* lw   = (const float*)d_in[9];
    const float* cw   = (const float*)d_in[10];
    const float* cb   = (const float*)d_in[11];
    float* out = (float*)d_out;
    int dup = (out_size >= 2*OUTN) ? 1 : 0;

    void* p;
    cudaGetSymbolAddress(&p, g_Hwb);    bf16* Hwb  = (bf16*)p;
    cudaGetSymbolAddress(&p, g_H2b);    bf16* H2b  = (bf16*)p;
    cudaGetSymbolAddress(&p, g_whh_bf); bf16* whhb = (bf16*)p;

    cudaFuncSetAttribute(k_zg1,    cudaFuncAttributeMaxDynamicSharedMemorySize, ZG_SMEM);
    cudaFuncSetAttribute(k_chain,  cudaFuncAttributeMaxDynamicSharedMemorySize, CH_SMEM);
    cudaFuncSetAttribute(k_logits, cudaFuncAttributeMaxDynamicSharedMemorySize, LG_SMEM);

    // launch 0: conversions + boundary scan
    k_conv_scan<<<CONV_BLOCKS + 8, 256>>>(enc, cw, w_ih, w_hh, lw, bnd);
    // launch 1: zin build (pe parallel; pool unrolled serial)
    k_build_zin<<<dim3(2, BATCH), 512>>>(enc, bnd, pos, ptab);
    // launch 2: fused z + G1 GEMM
    k_zg1<<<MROWS/128, 256, ZG_SMEM>>>(cb, b_ih, b_hh);
    // launch 3 (ncu lands here): carry chain
    k_chain<<<(BATCH/2)*4, 256, CH_SMEM>>>();
    // launch 4: H2 = Hw @ w_hh^T (ragged skip)
    k_gemm_mma<2><<<dim3(GATES/128, MROWS/128), 256>>>(Hwb, whhb, H2b, RNNH, GATES,
                                                        nullptr, nullptr);
    // launch 5: parallel per-step LSTM outputs
    k_apply<<<MROWS, 256>>>();
    // launch 6: logits + masking + log_softmax
    k_logits<<<MROWS/128, 256, LG_SMEM>>>(len, out, dup);
}